// round 1
// baseline (speedup 1.0000x reference)
#include <cuda_runtime.h>
#include <math.h>

#define BVn   32
#define SEQ   1024
#define DMOD  128
#define DI    256
#define DS    16
#define DFF   256
#define PLEN  16
#define DTR   8
#define NROWS (BVn*SEQ)   // 32768

// ---------------- scratch (static device globals; no allocation) ----------------
__device__ float g_hin[NROWS*PLEN];      // 0.5M  patch-transposed input
__device__ float g_h[NROWS*DMOD];        // 4M    running hidden state
__device__ float g_xz[NROWS*2*DI];       // 16M   in_proj output (x | z)
__device__ float g_xc[NROWS*DI];         // 8M    conv+silu output
__device__ float g_xdbl[NROWS*40];       // 1.3M  x_proj output (dt|B|C)
__device__ float g_delta[NROWS*DI];      // 8M
__device__ float g_y[NROWS*DI];          // 8M    scan output * silu(z)
__device__ float g_h2[NROWS*DMOD];       // 4M    out_proj output
__device__ float g_ff[NROWS*DFF];        // 8M    FFN hidden

// ---------------- kernel 1: x (bv,p,n) -> hin (bv*n, p) ----------------
__global__ void patch_transpose_kernel(const float* __restrict__ x, float* __restrict__ hin) {
    __shared__ float tile[PLEN][64 + 1];
    int bv = blockIdx.x;          // 32
    int nc = blockIdx.y;          // 16 chunks of 64 n
    int tid = threadIdx.x;        // 256
    const float* xb = x + (size_t)bv * PLEN * SEQ;
#pragma unroll
    for (int r = 0; r < 4; r++) {
        int idx = r * 256 + tid;
        int p = idx >> 6, nl = idx & 63;
        tile[p][nl] = xb[p * SEQ + nc * 64 + nl];
    }
    __syncthreads();
#pragma unroll
    for (int r = 0; r < 4; r++) {
        int nl = r * 16 + (tid >> 4);
        int p = tid & 15;
        hin[((size_t)bv * SEQ + nc * 64 + nl) * PLEN + p] = tile[p][nl];
    }
}

// ---------------- generic SGEMM: C[M,N] = A[M,K] @ W[N,K]^T (+bias, +act) ----------------
// ACT: 0 = none, 1 = exact GELU
// Requires: M multiple of 64, K multiple of 16.
template<int ACT>
__global__ void sgemm_kernel(const float* __restrict__ A, const float* __restrict__ W,
                             const float* __restrict__ bias, float* __restrict__ C,
                             int M, int N, int K) {
    __shared__ float As[16][64];
    __shared__ float Ws[16][64];
    const int tid = threadIdx.x;
    const int tx = tid & 15, ty = tid >> 4;
    const int brow = blockIdx.y << 6;
    const int bcol = blockIdx.x << 6;

    float acc[4][4];
#pragma unroll
    for (int i = 0; i < 4; i++)
#pragma unroll
        for (int j = 0; j < 4; j++) acc[i][j] = 0.f;

    const int lr = (tid * 4) >> 4;      // row/col index 0..63
    const int lk = (tid * 4) & 15;      // k offset 0..12 (mult of 4)

    for (int k0 = 0; k0 < K; k0 += 16) {
        // A tile (always in-bounds: M mult of 64)
        {
            const float4 v = *(const float4*)(A + (size_t)(brow + lr) * K + k0 + lk);
            As[lk + 0][lr] = v.x; As[lk + 1][lr] = v.y;
            As[lk + 2][lr] = v.z; As[lk + 3][lr] = v.w;
        }
        // W tile (mask cols >= N)
        {
            float4 v = make_float4(0.f, 0.f, 0.f, 0.f);
            int gcol = bcol + lr;
            if (gcol < N) v = *(const float4*)(W + (size_t)gcol * K + k0 + lk);
            Ws[lk + 0][lr] = v.x; Ws[lk + 1][lr] = v.y;
            Ws[lk + 2][lr] = v.z; Ws[lk + 3][lr] = v.w;
        }
        __syncthreads();
#pragma unroll
        for (int kk = 0; kk < 16; kk++) {
            const float4 av = *(const float4*)&As[kk][ty * 4];
            const float4 wv = *(const float4*)&Ws[kk][tx * 4];
            acc[0][0] += av.x * wv.x; acc[0][1] += av.x * wv.y;
            acc[0][2] += av.x * wv.z; acc[0][3] += av.x * wv.w;
            acc[1][0] += av.y * wv.x; acc[1][1] += av.y * wv.y;
            acc[1][2] += av.y * wv.z; acc[1][3] += av.y * wv.w;
            acc[2][0] += av.z * wv.x; acc[2][1] += av.z * wv.y;
            acc[2][2] += av.z * wv.z; acc[2][3] += av.z * wv.w;
            acc[3][0] += av.w * wv.x; acc[3][1] += av.w * wv.y;
            acc[3][2] += av.w * wv.z; acc[3][3] += av.w * wv.w;
        }
        __syncthreads();
    }

#pragma unroll
    for (int i = 0; i < 4; i++) {
        int row = brow + ty * 4 + i;
#pragma unroll
        for (int j = 0; j < 4; j++) {
            int col = bcol + tx * 4 + j;
            if (col < N) {
                float v = acc[i][j];
                if (bias) v += bias[col];
                if (ACT == 1) v = 0.5f * v * (1.0f + erff(v * 0.70710678118654752f));
                C[(size_t)row * N + col] = v;
            }
        }
    }
}

// ---------------- depthwise causal conv (k=4) + SiLU ----------------
// xin = xz[..., :256] (row stride 512). Output xc[bv,t,d].
__global__ void conv_silu_kernel(const float* __restrict__ xz, const float* __restrict__ cw,
                                 const float* __restrict__ cb, float* __restrict__ xc) {
    int bv = blockIdx.x;        // 32
    int chunk = blockIdx.y;     // 16 chunks of 64 t
    int d = threadIdx.x;        // 256
    float w0 = cw[d * 4 + 0], w1 = cw[d * 4 + 1], w2 = cw[d * 4 + 2], w3 = cw[d * 4 + 3];
    float bsv = cb[d];
    int t0 = chunk * 64;
    const float* base = xz + ((size_t)bv * SEQ) * (2 * DI) + d;
    float x0 = (t0 - 3 >= 0) ? base[(size_t)(t0 - 3) * (2 * DI)] : 0.f;
    float x1 = (t0 - 2 >= 0) ? base[(size_t)(t0 - 2) * (2 * DI)] : 0.f;
    float x2 = (t0 - 1 >= 0) ? base[(size_t)(t0 - 1) * (2 * DI)] : 0.f;
#pragma unroll 4
    for (int tt = 0; tt < 64; tt++) {
        int t = t0 + tt;
        float x3 = base[(size_t)t * (2 * DI)];
        float v = w0 * x0 + w1 * x1 + w2 * x2 + w3 * x3 + bsv;
        float s = v / (1.0f + __expf(-v));          // silu
        xc[((size_t)bv * SEQ + t) * DI + d] = s;
        x0 = x1; x1 = x2; x2 = x3;
    }
}

// ---------------- dt_proj (K=8) + softplus ----------------
__global__ void dt_softplus_kernel(const float* __restrict__ xdbl, const float* __restrict__ dtw,
                                   const float* __restrict__ dtb, float* __restrict__ delta) {
    int row = blockIdx.x;       // 32768
    int d = threadIdx.x;        // 256
    __shared__ float dts[DTR];
    if (d < DTR) dts[d] = xdbl[(size_t)row * 40 + d];
    __syncthreads();
    float acc = dtb[d];
#pragma unroll
    for (int r = 0; r < DTR; r++) acc += dts[r] * dtw[d * DTR + r];
    float sp = (acc > 20.f) ? acc : log1pf(__expf(acc));
    delta[(size_t)row * DI + d] = sp;
}

// ---------------- selective scan (fused +u*D and *silu(z)) ----------------
// warp = 2 d-channels, 16 state lanes each
__global__ void scan_kernel(const float* __restrict__ xc, const float* __restrict__ delta,
                            const float* __restrict__ xdbl, const float* __restrict__ xz,
                            const float* __restrict__ A_log, const float* __restrict__ Dp,
                            float* __restrict__ y) {
    int w = (blockIdx.x * blockDim.x + threadIdx.x) >> 5;     // 0..4095
    int lane = threadIdx.x & 31;
    int bv = w >> 7;              // /128
    int dp = w & 127;
    int s = lane & 15;
    int d = dp * 2 + (lane >> 4);

    float a = -__expf(A_log[d * DS + s]);
    float Dval = Dp[d];
    float h = 0.f;

    const size_t rbase = (size_t)bv * SEQ;
    for (int t = 0; t < SEQ; t++) {
        size_t rbt = rbase + t;
        float u  = xc[rbt * DI + d];
        float dl = delta[rbt * DI + d];
        float Bv = xdbl[rbt * 40 + DTR + s];
        float Cv = xdbl[rbt * 40 + DTR + DS + s];
        float dA = __expf(dl * a);
        h = dA * h + (dl * u) * Bv;
        float p = h * Cv;
        p += __shfl_xor_sync(0xffffffffu, p, 1, 16);
        p += __shfl_xor_sync(0xffffffffu, p, 2, 16);
        p += __shfl_xor_sync(0xffffffffu, p, 4, 16);
        p += __shfl_xor_sync(0xffffffffu, p, 8, 16);
        if (s == 0) {
            float zv = xz[rbt * (2 * DI) + DI + d];
            float silz = zv / (1.0f + __expf(-zv));
            y[rbt * DI + d] = (p + u * Dval) * silz;
        }
    }
}

// ---------------- final transpose: h[bv,n,dm] -> out[bv,dm,n] ----------------
__global__ void out_transpose_kernel(const float* __restrict__ hbuf, float* __restrict__ out) {
    __shared__ float tile[32][33];
    int bv = blockIdx.x, nc = blockIdx.y, dc = blockIdx.z;
    int tx = threadIdx.x, ty = threadIdx.y;
    tile[ty][tx] = hbuf[((size_t)bv * SEQ + nc * 32 + ty) * DMOD + dc * 32 + tx];
    __syncthreads();
    out[((size_t)bv * DMOD + dc * 32 + ty) * SEQ + nc * 32 + tx] = tile[tx][ty];
}

// ---------------- launch ----------------
extern "C" void kernel_launch(void* const* d_in, const int* in_sizes, int n_in,
                              void* d_out, int out_size) {
    const float* x         = (const float*)d_in[0];
    const float* W_P_w     = (const float*)d_in[1];
    const float* W_P_b     = (const float*)d_in[2];
    const float* in_proj_w = (const float*)d_in[3];
    const float* conv_w    = (const float*)d_in[4];
    const float* conv_b    = (const float*)d_in[5];
    const float* x_proj_w  = (const float*)d_in[6];
    const float* dt_proj_w = (const float*)d_in[7];
    const float* dt_proj_b = (const float*)d_in[8];
    const float* A_log     = (const float*)d_in[9];
    const float* Dp        = (const float*)d_in[10];
    const float* out_proj_w= (const float*)d_in[11];
    const float* lin1_w    = (const float*)d_in[12];
    const float* lin1_b    = (const float*)d_in[13];
    const float* lin2_w    = (const float*)d_in[14];
    const float* lin2_b    = (const float*)d_in[15];
    float* out = (float*)d_out;

    float *hin, *h, *xz, *xc, *xdbl, *delta, *y, *h2, *ff;
    cudaGetSymbolAddress((void**)&hin,   g_hin);
    cudaGetSymbolAddress((void**)&h,     g_h);
    cudaGetSymbolAddress((void**)&xz,    g_xz);
    cudaGetSymbolAddress((void**)&xc,    g_xc);
    cudaGetSymbolAddress((void**)&xdbl,  g_xdbl);
    cudaGetSymbolAddress((void**)&delta, g_delta);
    cudaGetSymbolAddress((void**)&y,     g_y);
    cudaGetSymbolAddress((void**)&h2,    g_h2);
    cudaGetSymbolAddress((void**)&ff,    g_ff);

    const int MB = NROWS / 64;   // 512 row blocks

    // patch embed
    patch_transpose_kernel<<<dim3(32, 16), 256>>>(x, hin);
    sgemm_kernel<0><<<dim3(2, MB), 256>>>(hin, W_P_w, W_P_b, h, NROWS, DMOD, PLEN);

    for (int l = 0; l < 2; l++) {
        const float* ipw = in_proj_w  + (size_t)l * (2 * DI) * DMOD;
        const float* cwp = conv_w     + (size_t)l * DI * 4;
        const float* cbp = conv_b     + (size_t)l * DI;
        const float* xpw = x_proj_w   + (size_t)l * 40 * DI;
        const float* dpw = dt_proj_w  + (size_t)l * DI * DTR;
        const float* dpb = dt_proj_b  + (size_t)l * DI;
        const float* alg = A_log      + (size_t)l * DI * DS;
        const float* dvp = Dp         + (size_t)l * DI;
        const float* opw = out_proj_w + (size_t)l * DMOD * DI;
        const float* l1w = lin1_w     + (size_t)l * DFF * DMOD;
        const float* l1b = lin1_b     + (size_t)l * DFF;
        const float* l2w = lin2_w     + (size_t)l * DMOD * DFF;
        const float* l2b = lin2_b     + (size_t)l * DMOD;

        sgemm_kernel<0><<<dim3(8, MB), 256>>>(h, ipw, nullptr, xz, NROWS, 2 * DI, DMOD);
        conv_silu_kernel<<<dim3(32, 16), 256>>>(xz, cwp, cbp, xc);
        sgemm_kernel<0><<<dim3(1, MB), 256>>>(xc, xpw, nullptr, xdbl, NROWS, 40, DI);
        dt_softplus_kernel<<<NROWS, 256>>>(xdbl, dpw, dpb, delta);
        scan_kernel<<<1024, 128>>>(xc, delta, xdbl, xz, alg, dvp, y);
        sgemm_kernel<0><<<dim3(2, MB), 256>>>(y, opw, nullptr, h2, NROWS, DMOD, DI);
        sgemm_kernel<1><<<dim3(4, MB), 256>>>(h2, l1w, l1b, ff, NROWS, DFF, DMOD);
        sgemm_kernel<0><<<dim3(2, MB), 256>>>(ff, l2w, l2b, h, NROWS, DMOD, DFF);
    }

    out_transpose_kernel<<<dim3(32, 32, 4), dim3(32, 32)>>>(h, out);
}

// round 2
// speedup vs baseline: 1.0427x; 1.0427x over previous
#include <cuda_runtime.h>
#include <math.h>

#define BVn   32
#define SEQ   1024
#define DMOD  128
#define DI    256
#define DS    16
#define DFF   256
#define PLEN  16
#define DTR   8
#define NROWS (BVn*SEQ)   // 32768

// ---------------- scratch (static device globals; no allocation) ----------------
__device__ float g_hin[NROWS*PLEN];
__device__ float g_h[NROWS*DMOD];
__device__ float g_xz[NROWS*2*DI];
__device__ float g_xc[NROWS*DI];
__device__ float g_xdbl[NROWS*40];
__device__ float g_delta[NROWS*DI];
__device__ float g_y[NROWS*DI];
__device__ float g_h2[NROWS*DMOD];
__device__ float g_ff[NROWS*DFF];

// ---------------- kernel 1: x (bv,p,n) -> hin (bv*n, p) ----------------
__global__ void patch_transpose_kernel(const float* __restrict__ x, float* __restrict__ hin) {
    __shared__ float tile[PLEN][64 + 1];
    int bv = blockIdx.x;
    int nc = blockIdx.y;
    int tid = threadIdx.x;
    const float* xb = x + (size_t)bv * PLEN * SEQ;
#pragma unroll
    for (int r = 0; r < 4; r++) {
        int idx = r * 256 + tid;
        int p = idx >> 6, nl = idx & 63;
        tile[p][nl] = xb[p * SEQ + nc * 64 + nl];
    }
    __syncthreads();
#pragma unroll
    for (int r = 0; r < 4; r++) {
        int nl = r * 16 + (tid >> 4);
        int p = tid & 15;
        hin[((size_t)bv * SEQ + nc * 64 + nl) * PLEN + p] = tile[p][nl];
    }
}

// ---------------- big SGEMM: C[M,N] = A[M,K] @ W[N,K]^T (+bias, +act) ----------------
// 128x128 tile, BK=16, 256 threads, 8x8 microtile, double-buffered smem.
// Requires: M % 128 == 0, N % 128 == 0, K % 16 == 0.
template<int ACT>
__global__ void __launch_bounds__(256, 2)
sgemm128_kernel(const float* __restrict__ A, const float* __restrict__ W,
                const float* __restrict__ bias, float* __restrict__ C,
                int M, int N, int K) {
    __shared__ float As[2][16][128];
    __shared__ float Ws[2][16][128];
    const int tid = threadIdx.x;
    const int brow = blockIdx.y << 7;
    const int bcol = blockIdx.x << 7;
    const int tx = tid & 15;       // col group (8 cols)
    const int ty = tid >> 4;       // row group (8 rows)

    // Load mapping: each thread loads 2 float4 per operand tile.
    // row = tid>>1 ; even tid covers k[0..7], odd tid covers k[8..15].
    const int l_row = tid >> 1;
    const int l_k0  = ((tid * 2) & 3) * 4;   // 0 or 8

    const float* Arow = A + (size_t)(brow + l_row) * K + l_k0;
    const float* Wrow = W + (size_t)(bcol + l_row) * K + l_k0;

    float acc[8][8];
#pragma unroll
    for (int i = 0; i < 8; i++)
#pragma unroll
        for (int j = 0; j < 8; j++) acc[i][j] = 0.f;

    float4 pA0, pA1, pW0, pW1;

    // prefetch tile 0
    pA0 = *(const float4*)(Arow);
    pA1 = *(const float4*)(Arow + 4);
    pW0 = *(const float4*)(Wrow);
    pW1 = *(const float4*)(Wrow + 4);
    {
        As[0][l_k0 + 0][l_row] = pA0.x; As[0][l_k0 + 1][l_row] = pA0.y;
        As[0][l_k0 + 2][l_row] = pA0.z; As[0][l_k0 + 3][l_row] = pA0.w;
        As[0][l_k0 + 4][l_row] = pA1.x; As[0][l_k0 + 5][l_row] = pA1.y;
        As[0][l_k0 + 6][l_row] = pA1.z; As[0][l_k0 + 7][l_row] = pA1.w;
        Ws[0][l_k0 + 0][l_row] = pW0.x; Ws[0][l_k0 + 1][l_row] = pW0.y;
        Ws[0][l_k0 + 2][l_row] = pW0.z; Ws[0][l_k0 + 3][l_row] = pW0.w;
        Ws[0][l_k0 + 4][l_row] = pW1.x; Ws[0][l_k0 + 5][l_row] = pW1.y;
        Ws[0][l_k0 + 6][l_row] = pW1.z; Ws[0][l_k0 + 7][l_row] = pW1.w;
    }
    __syncthreads();

    const int nk = K >> 4;
    int buf = 0;
    for (int kt = 0; kt < nk; kt++) {
        const bool more = (kt + 1 < nk);
        if (more) {
            const float* Ar = Arow + (kt + 1) * 16;
            const float* Wr = Wrow + (kt + 1) * 16;
            pA0 = *(const float4*)(Ar);
            pA1 = *(const float4*)(Ar + 4);
            pW0 = *(const float4*)(Wr);
            pW1 = *(const float4*)(Wr + 4);
        }

#pragma unroll
        for (int kk = 0; kk < 16; kk++) {
            float4 a0 = *(const float4*)&As[buf][kk][ty * 8];
            float4 a1 = *(const float4*)&As[buf][kk][ty * 8 + 4];
            float4 w0 = *(const float4*)&Ws[buf][kk][tx * 8];
            float4 w1 = *(const float4*)&Ws[buf][kk][tx * 8 + 4];
            float av[8] = {a0.x, a0.y, a0.z, a0.w, a1.x, a1.y, a1.z, a1.w};
            float wv[8] = {w0.x, w0.y, w0.z, w0.w, w1.x, w1.y, w1.z, w1.w};
#pragma unroll
            for (int i = 0; i < 8; i++)
#pragma unroll
                for (int j = 0; j < 8; j++)
                    acc[i][j] += av[i] * wv[j];
        }

        if (more) {
            int nb = buf ^ 1;
            As[nb][l_k0 + 0][l_row] = pA0.x; As[nb][l_k0 + 1][l_row] = pA0.y;
            As[nb][l_k0 + 2][l_row] = pA0.z; As[nb][l_k0 + 3][l_row] = pA0.w;
            As[nb][l_k0 + 4][l_row] = pA1.x; As[nb][l_k0 + 5][l_row] = pA1.y;
            As[nb][l_k0 + 6][l_row] = pA1.z; As[nb][l_k0 + 7][l_row] = pA1.w;
            Ws[nb][l_k0 + 0][l_row] = pW0.x; Ws[nb][l_k0 + 1][l_row] = pW0.y;
            Ws[nb][l_k0 + 2][l_row] = pW0.z; Ws[nb][l_k0 + 3][l_row] = pW0.w;
            Ws[nb][l_k0 + 4][l_row] = pW1.x; Ws[nb][l_k0 + 5][l_row] = pW1.y;
            Ws[nb][l_k0 + 6][l_row] = pW1.z; Ws[nb][l_k0 + 7][l_row] = pW1.w;
            __syncthreads();
            buf = nb;
        }
    }

    // epilogue
    float bv[8];
#pragma unroll
    for (int j = 0; j < 8; j++) bv[j] = bias ? bias[bcol + tx * 8 + j] : 0.f;

#pragma unroll
    for (int i = 0; i < 8; i++) {
        int row = brow + ty * 8 + i;
        float v[8];
#pragma unroll
        for (int j = 0; j < 8; j++) {
            float t = acc[i][j] + bv[j];
            if (ACT == 1) t = 0.5f * t * (1.0f + erff(t * 0.70710678118654752f));
            v[j] = t;
        }
        float* cp = C + (size_t)row * N + bcol + tx * 8;
        *(float4*)(cp)     = make_float4(v[0], v[1], v[2], v[3]);
        *(float4*)(cp + 4) = make_float4(v[4], v[5], v[6], v[7]);
    }
}

// ---------------- small SGEMM (64x64) for N=40 x_proj ----------------
template<int ACT>
__global__ void sgemm_kernel(const float* __restrict__ A, const float* __restrict__ W,
                             const float* __restrict__ bias, float* __restrict__ C,
                             int M, int N, int K) {
    __shared__ float As[16][64];
    __shared__ float Ws[16][64];
    const int tid = threadIdx.x;
    const int tx = tid & 15, ty = tid >> 4;
    const int brow = blockIdx.y << 6;
    const int bcol = blockIdx.x << 6;

    float acc[4][4];
#pragma unroll
    for (int i = 0; i < 4; i++)
#pragma unroll
        for (int j = 0; j < 4; j++) acc[i][j] = 0.f;

    const int lr = (tid * 4) >> 4;
    const int lk = (tid * 4) & 15;

    for (int k0 = 0; k0 < K; k0 += 16) {
        {
            const float4 v = *(const float4*)(A + (size_t)(brow + lr) * K + k0 + lk);
            As[lk + 0][lr] = v.x; As[lk + 1][lr] = v.y;
            As[lk + 2][lr] = v.z; As[lk + 3][lr] = v.w;
        }
        {
            float4 v = make_float4(0.f, 0.f, 0.f, 0.f);
            int gcol = bcol + lr;
            if (gcol < N) v = *(const float4*)(W + (size_t)gcol * K + k0 + lk);
            Ws[lk + 0][lr] = v.x; Ws[lk + 1][lr] = v.y;
            Ws[lk + 2][lr] = v.z; Ws[lk + 3][lr] = v.w;
        }
        __syncthreads();
#pragma unroll
        for (int kk = 0; kk < 16; kk++) {
            const float4 av = *(const float4*)&As[kk][ty * 4];
            const float4 wv = *(const float4*)&Ws[kk][tx * 4];
            acc[0][0] += av.x * wv.x; acc[0][1] += av.x * wv.y;
            acc[0][2] += av.x * wv.z; acc[0][3] += av.x * wv.w;
            acc[1][0] += av.y * wv.x; acc[1][1] += av.y * wv.y;
            acc[1][2] += av.y * wv.z; acc[1][3] += av.y * wv.w;
            acc[2][0] += av.z * wv.x; acc[2][1] += av.z * wv.y;
            acc[2][2] += av.z * wv.z; acc[2][3] += av.z * wv.w;
            acc[3][0] += av.w * wv.x; acc[3][1] += av.w * wv.y;
            acc[3][2] += av.w * wv.z; acc[3][3] += av.w * wv.w;
        }
        __syncthreads();
    }

#pragma unroll
    for (int i = 0; i < 4; i++) {
        int row = brow + ty * 4 + i;
#pragma unroll
        for (int j = 0; j < 4; j++) {
            int col = bcol + tx * 4 + j;
            if (col < N) {
                float v = acc[i][j];
                if (bias) v += bias[col];
                if (ACT == 1) v = 0.5f * v * (1.0f + erff(v * 0.70710678118654752f));
                C[(size_t)row * N + col] = v;
            }
        }
    }
}

// ---------------- depthwise causal conv (k=4) + SiLU ----------------
__global__ void conv_silu_kernel(const float* __restrict__ xz, const float* __restrict__ cw,
                                 const float* __restrict__ cb, float* __restrict__ xc) {
    int bv = blockIdx.x;
    int chunk = blockIdx.y;
    int d = threadIdx.x;
    float w0 = cw[d * 4 + 0], w1 = cw[d * 4 + 1], w2 = cw[d * 4 + 2], w3 = cw[d * 4 + 3];
    float bsv = cb[d];
    int t0 = chunk * 64;
    const float* base = xz + ((size_t)bv * SEQ) * (2 * DI) + d;
    float x0 = (t0 - 3 >= 0) ? base[(size_t)(t0 - 3) * (2 * DI)] : 0.f;
    float x1 = (t0 - 2 >= 0) ? base[(size_t)(t0 - 2) * (2 * DI)] : 0.f;
    float x2 = (t0 - 1 >= 0) ? base[(size_t)(t0 - 1) * (2 * DI)] : 0.f;
#pragma unroll 4
    for (int tt = 0; tt < 64; tt++) {
        int t = t0 + tt;
        float x3 = base[(size_t)t * (2 * DI)];
        float v = w0 * x0 + w1 * x1 + w2 * x2 + w3 * x3 + bsv;
        float s = v / (1.0f + __expf(-v));
        xc[((size_t)bv * SEQ + t) * DI + d] = s;
        x0 = x1; x1 = x2; x2 = x3;
    }
}

// ---------------- dt_proj (K=8) + softplus ----------------
__global__ void dt_softplus_kernel(const float* __restrict__ xdbl, const float* __restrict__ dtw,
                                   const float* __restrict__ dtb, float* __restrict__ delta) {
    int row = blockIdx.x;
    int d = threadIdx.x;
    __shared__ float dts[DTR];
    if (d < DTR) dts[d] = xdbl[(size_t)row * 40 + d];
    __syncthreads();
    float acc = dtb[d];
#pragma unroll
    for (int r = 0; r < DTR; r++) acc += dts[r] * dtw[d * DTR + r];
    float sp = (acc > 20.f) ? acc : log1pf(__expf(acc));
    delta[(size_t)row * DI + d] = sp;
}

// ---------------- selective scan (fused +u*D and *silu(z)) ----------------
__global__ void scan_kernel(const float* __restrict__ xc, const float* __restrict__ delta,
                            const float* __restrict__ xdbl, const float* __restrict__ xz,
                            const float* __restrict__ A_log, const float* __restrict__ Dp,
                            float* __restrict__ y) {
    int w = (blockIdx.x * blockDim.x + threadIdx.x) >> 5;
    int lane = threadIdx.x & 31;
    int bv = w >> 7;
    int dp = w & 127;
    int s = lane & 15;
    int d = dp * 2 + (lane >> 4);

    float a = -__expf(A_log[d * DS + s]);
    float Dval = Dp[d];
    float h = 0.f;

    const size_t rbase = (size_t)bv * SEQ;
    for (int t = 0; t < SEQ; t++) {
        size_t rbt = rbase + t;
        float u  = xc[rbt * DI + d];
        float dl = delta[rbt * DI + d];
        float Bv = xdbl[rbt * 40 + DTR + s];
        float Cv = xdbl[rbt * 40 + DTR + DS + s];
        float dA = __expf(dl * a);
        h = dA * h + (dl * u) * Bv;
        float p = h * Cv;
        p += __shfl_xor_sync(0xffffffffu, p, 1, 16);
        p += __shfl_xor_sync(0xffffffffu, p, 2, 16);
        p += __shfl_xor_sync(0xffffffffu, p, 4, 16);
        p += __shfl_xor_sync(0xffffffffu, p, 8, 16);
        if (s == 0) {
            float zv = xz[rbt * (2 * DI) + DI + d];
            float silz = zv / (1.0f + __expf(-zv));
            y[rbt * DI + d] = (p + u * Dval) * silz;
        }
    }
}

// ---------------- final transpose: h[bv,n,dm] -> out[bv,dm,n] ----------------
__global__ void out_transpose_kernel(const float* __restrict__ hbuf, float* __restrict__ out) {
    __shared__ float tile[32][33];
    int bv = blockIdx.x, nc = blockIdx.y, dc = blockIdx.z;
    int tx = threadIdx.x, ty = threadIdx.y;
    tile[ty][tx] = hbuf[((size_t)bv * SEQ + nc * 32 + ty) * DMOD + dc * 32 + tx];
    __syncthreads();
    out[((size_t)bv * DMOD + dc * 32 + ty) * SEQ + nc * 32 + tx] = tile[tx][ty];
}

// ---------------- launch ----------------
extern "C" void kernel_launch(void* const* d_in, const int* in_sizes, int n_in,
                              void* d_out, int out_size) {
    const float* x         = (const float*)d_in[0];
    const float* W_P_w     = (const float*)d_in[1];
    const float* W_P_b     = (const float*)d_in[2];
    const float* in_proj_w = (const float*)d_in[3];
    const float* conv_w    = (const float*)d_in[4];
    const float* conv_b    = (const float*)d_in[5];
    const float* x_proj_w  = (const float*)d_in[6];
    const float* dt_proj_w = (const float*)d_in[7];
    const float* dt_proj_b = (const float*)d_in[8];
    const float* A_log     = (const float*)d_in[9];
    const float* Dp        = (const float*)d_in[10];
    const float* out_proj_w= (const float*)d_in[11];
    const float* lin1_w    = (const float*)d_in[12];
    const float* lin1_b    = (const float*)d_in[13];
    const float* lin2_w    = (const float*)d_in[14];
    const float* lin2_b    = (const float*)d_in[15];
    float* out = (float*)d_out;

    float *hin, *h, *xz, *xc, *xdbl, *delta, *y, *h2, *ff;
    cudaGetSymbolAddress((void**)&hin,   g_hin);
    cudaGetSymbolAddress((void**)&h,     g_h);
    cudaGetSymbolAddress((void**)&xz,    g_xz);
    cudaGetSymbolAddress((void**)&xc,    g_xc);
    cudaGetSymbolAddress((void**)&xdbl,  g_xdbl);
    cudaGetSymbolAddress((void**)&delta, g_delta);
    cudaGetSymbolAddress((void**)&y,     g_y);
    cudaGetSymbolAddress((void**)&h2,    g_h2);
    cudaGetSymbolAddress((void**)&ff,    g_ff);

    const int MB128 = NROWS / 128;   // 256 row blocks

    patch_transpose_kernel<<<dim3(32, 16), 256>>>(x, hin);
    sgemm128_kernel<0><<<dim3(1, MB128), 256>>>(hin, W_P_w, W_P_b, h, NROWS, DMOD, PLEN);

    for (int l = 0; l < 2; l++) {
        const float* ipw = in_proj_w  + (size_t)l * (2 * DI) * DMOD;
        const float* cwp = conv_w     + (size_t)l * DI * 4;
        const float* cbp = conv_b     + (size_t)l * DI;
        const float* xpw = x_proj_w   + (size_t)l * 40 * DI;
        const float* dpw = dt_proj_w  + (size_t)l * DI * DTR;
        const float* dpb = dt_proj_b  + (size_t)l * DI;
        const float* alg = A_log      + (size_t)l * DI * DS;
        const float* dvp = Dp         + (size_t)l * DI;
        const float* opw = out_proj_w + (size_t)l * DMOD * DI;
        const float* l1w = lin1_w     + (size_t)l * DFF * DMOD;
        const float* l1b = lin1_b     + (size_t)l * DFF;
        const float* l2w = lin2_w     + (size_t)l * DMOD * DFF;
        const float* l2b = lin2_b     + (size_t)l * DMOD;

        sgemm128_kernel<0><<<dim3(4, MB128), 256>>>(h, ipw, nullptr, xz, NROWS, 2 * DI, DMOD);
        conv_silu_kernel<<<dim3(32, 16), 256>>>(xz, cwp, cbp, xc);
        sgemm_kernel<0><<<dim3(1, NROWS / 64), 256>>>(xc, xpw, nullptr, xdbl, NROWS, 40, DI);
        dt_softplus_kernel<<<NROWS, 256>>>(xdbl, dpw, dpb, delta);
        scan_kernel<<<1024, 128>>>(xc, delta, xdbl, xz, alg, dvp, y);
        sgemm128_kernel<0><<<dim3(1, MB128), 256>>>(y, opw, nullptr, h2, NROWS, DMOD, DI);
        sgemm128_kernel<1><<<dim3(2, MB128), 256>>>(h2, l1w, l1b, ff, NROWS, DFF, DMOD);
        sgemm128_kernel<0><<<dim3(1, MB128), 256>>>(ff, l2w, l2b, h, NROWS, DMOD, DFF);
    }

    out_transpose_kernel<<<dim3(32, 32, 4), dim3(32, 32)>>>(h, out);
}

// round 3
// speedup vs baseline: 1.1459x; 1.0990x over previous
#include <cuda_runtime.h>
#include <math.h>
#include <stdint.h>

#define BVn   32
#define SEQ   1024
#define DMOD  128
#define DI    256
#define DS    16
#define DFF   256
#define PLEN  16
#define DTR   8
#define NROWS (BVn*SEQ)   // 32768

// ---------------- scratch (static device globals; no allocation) ----------------
__device__ float g_hin[NROWS*PLEN];
__device__ float g_h[NROWS*DMOD];
__device__ float g_xz[NROWS*2*DI];
__device__ float g_xc[NROWS*DI];
__device__ float g_xdbl[NROWS*40];
__device__ float g_delta[NROWS*DI];
__device__ float g_y[NROWS*DI];
__device__ float g_h2[NROWS*DMOD];
__device__ float g_ff[NROWS*DFF];

// ---------------- kernel 1: x (bv,p,n) -> hin (bv*n, p) ----------------
__global__ void patch_transpose_kernel(const float* __restrict__ x, float* __restrict__ hin) {
    __shared__ float tile[PLEN][64 + 1];
    int bv = blockIdx.x;
    int nc = blockIdx.y;
    int tid = threadIdx.x;
    const float* xb = x + (size_t)bv * PLEN * SEQ;
#pragma unroll
    for (int r = 0; r < 4; r++) {
        int idx = r * 256 + tid;
        int p = idx >> 6, nl = idx & 63;
        tile[p][nl] = xb[p * SEQ + nc * 64 + nl];
    }
    __syncthreads();
#pragma unroll
    for (int r = 0; r < 4; r++) {
        int nl = r * 16 + (tid >> 4);
        int p = tid & 15;
        hin[((size_t)bv * SEQ + nc * 64 + nl) * PLEN + p] = tile[p][nl];
    }
}

// ---------------- tf32 helpers ----------------
__device__ __forceinline__ uint32_t f2tf32(float f) {
    uint32_t r;
    asm("cvt.rna.tf32.f32 %0, %1;" : "=r"(r) : "f"(f));
    return r;
}

__device__ __forceinline__ void mma_tf32(float* d, const uint32_t* a, const uint32_t* b) {
    asm volatile(
        "mma.sync.aligned.m16n8k8.row.col.f32.tf32.tf32.f32 "
        "{%0,%1,%2,%3}, {%4,%5,%6,%7}, {%8,%9}, {%0,%1,%2,%3};"
        : "+f"(d[0]), "+f"(d[1]), "+f"(d[2]), "+f"(d[3])
        : "r"(a[0]), "r"(a[1]), "r"(a[2]), "r"(a[3]), "r"(b[0]), "r"(b[1]));
}

// ---------------- tf32 tensor-core GEMM ----------------
// C[M,N] = A[M,K] @ W[N,K]^T (+bias, +GELU)
// CTA tile 128x128, BK=16 double-buffered, 8 warps of 64x32.
// Requires: M%128==0, N%128==0, K%16==0.
#define TG_STRIDE 20   // 16 + 4 pad, conflict-free for fragment access
template<int ACT>
__global__ void __launch_bounds__(256)
tgemm_kernel(const float* __restrict__ A, const float* __restrict__ W,
             const float* __restrict__ bias, float* __restrict__ C,
             int M, int N, int K) {
    __shared__ uint32_t As[2][128 * TG_STRIDE];
    __shared__ uint32_t Ws[2][128 * TG_STRIDE];

    const int tid  = threadIdx.x;
    const int warp = tid >> 5;
    const int lane = tid & 31;
    const int gid  = lane >> 2;      // 0..7
    const int tig  = lane & 3;       // 0..3
    const int warp_m = warp >> 2;    // 0..1
    const int warp_n = warp & 3;     // 0..3

    const int brow = blockIdx.y << 7;
    const int bcol = blockIdx.x << 7;

    // global load mapping: each thread 8 consecutive k of one row (2 float4)
    const int l_row = tid >> 1;
    const int l_k0  = (tid & 1) * 8;
    const float* Ag = A + (size_t)(brow + l_row) * K + l_k0;
    const float* Wg = W + (size_t)(bcol + l_row) * K + l_k0;
    const int s_off = l_row * TG_STRIDE + l_k0;

    float acc[4][4][4];
#pragma unroll
    for (int i = 0; i < 4; i++)
#pragma unroll
        for (int j = 0; j < 4; j++)
#pragma unroll
            for (int r = 0; r < 4; r++) acc[i][j][r] = 0.f;

    float4 a0, a1, w0, w1;
    a0 = *(const float4*)(Ag);
    a1 = *(const float4*)(Ag + 4);
    w0 = *(const float4*)(Wg);
    w1 = *(const float4*)(Wg + 4);
    {
        uint4 ua = make_uint4(f2tf32(a0.x), f2tf32(a0.y), f2tf32(a0.z), f2tf32(a0.w));
        uint4 ub = make_uint4(f2tf32(a1.x), f2tf32(a1.y), f2tf32(a1.z), f2tf32(a1.w));
        *(uint4*)&As[0][s_off]     = ua;
        *(uint4*)&As[0][s_off + 4] = ub;
        uint4 uc = make_uint4(f2tf32(w0.x), f2tf32(w0.y), f2tf32(w0.z), f2tf32(w0.w));
        uint4 ud = make_uint4(f2tf32(w1.x), f2tf32(w1.y), f2tf32(w1.z), f2tf32(w1.w));
        *(uint4*)&Ws[0][s_off]     = uc;
        *(uint4*)&Ws[0][s_off + 4] = ud;
    }
    __syncthreads();

    const int nk = K >> 4;
    int buf = 0;
    for (int kt = 0; kt < nk; kt++) {
        const bool more = (kt + 1 < nk);
        if (more) {
            const float* Ar = Ag + (kt + 1) * 16;
            const float* Wr = Wg + (kt + 1) * 16;
            a0 = *(const float4*)(Ar);
            a1 = *(const float4*)(Ar + 4);
            w0 = *(const float4*)(Wr);
            w1 = *(const float4*)(Wr + 4);
        }

        const uint32_t* Ab = As[buf];
        const uint32_t* Wb = Ws[buf];
#pragma unroll
        for (int ks = 0; ks < 16; ks += 8) {
            uint32_t afr[4][4];
#pragma unroll
            for (int mf = 0; mf < 4; mf++) {
                int r0 = (warp_m * 64 + mf * 16 + gid) * TG_STRIDE + ks + tig;
                afr[mf][0] = Ab[r0];
                afr[mf][1] = Ab[r0 + 8 * TG_STRIDE];
                afr[mf][2] = Ab[r0 + 4];
                afr[mf][3] = Ab[r0 + 8 * TG_STRIDE + 4];
            }
            uint32_t bfr[4][2];
#pragma unroll
            for (int nf = 0; nf < 4; nf++) {
                int n0 = (warp_n * 32 + nf * 8 + gid) * TG_STRIDE + ks + tig;
                bfr[nf][0] = Wb[n0];
                bfr[nf][1] = Wb[n0 + 4];
            }
#pragma unroll
            for (int mf = 0; mf < 4; mf++)
#pragma unroll
                for (int nf = 0; nf < 4; nf++)
                    mma_tf32(acc[mf][nf], afr[mf], bfr[nf]);
        }

        if (more) {
            int nb = buf ^ 1;
            uint4 ua = make_uint4(f2tf32(a0.x), f2tf32(a0.y), f2tf32(a0.z), f2tf32(a0.w));
            uint4 ub = make_uint4(f2tf32(a1.x), f2tf32(a1.y), f2tf32(a1.z), f2tf32(a1.w));
            *(uint4*)&As[nb][s_off]     = ua;
            *(uint4*)&As[nb][s_off + 4] = ub;
            uint4 uc = make_uint4(f2tf32(w0.x), f2tf32(w0.y), f2tf32(w0.z), f2tf32(w0.w));
            uint4 ud = make_uint4(f2tf32(w1.x), f2tf32(w1.y), f2tf32(w1.z), f2tf32(w1.w));
            *(uint4*)&Ws[nb][s_off]     = uc;
            *(uint4*)&Ws[nb][s_off + 4] = ud;
            __syncthreads();
            buf = nb;
        }
    }

    // epilogue: acc[mf][nf] layout -> c(row=gid/gid+8, col=tig*2, tig*2+1)
#pragma unroll
    for (int mf = 0; mf < 4; mf++) {
        int r0 = brow + warp_m * 64 + mf * 16 + gid;
#pragma unroll
        for (int nf = 0; nf < 4; nf++) {
            int c0 = bcol + warp_n * 32 + nf * 8 + tig * 2;
            float b0 = bias ? bias[c0] : 0.f;
            float b1 = bias ? bias[c0 + 1] : 0.f;
            float v0 = acc[mf][nf][0] + b0;
            float v1 = acc[mf][nf][1] + b1;
            float v2 = acc[mf][nf][2] + b0;
            float v3 = acc[mf][nf][3] + b1;
            if (ACT == 1) {
                v0 = 0.5f * v0 * (1.0f + erff(v0 * 0.70710678118654752f));
                v1 = 0.5f * v1 * (1.0f + erff(v1 * 0.70710678118654752f));
                v2 = 0.5f * v2 * (1.0f + erff(v2 * 0.70710678118654752f));
                v3 = 0.5f * v3 * (1.0f + erff(v3 * 0.70710678118654752f));
            }
            *(float2*)(C + (size_t)r0 * N + c0)       = make_float2(v0, v1);
            *(float2*)(C + (size_t)(r0 + 8) * N + c0) = make_float2(v2, v3);
        }
    }
}

// ---------------- small SGEMM (64x64) for N=40 x_proj (fp32, precision-critical) ----------------
template<int ACT>
__global__ void sgemm_kernel(const float* __restrict__ A, const float* __restrict__ W,
                             const float* __restrict__ bias, float* __restrict__ C,
                             int M, int N, int K) {
    __shared__ float As[16][64];
    __shared__ float Ws[16][64];
    const int tid = threadIdx.x;
    const int tx = tid & 15, ty = tid >> 4;
    const int brow = blockIdx.y << 6;
    const int bcol = blockIdx.x << 6;

    float acc[4][4];
#pragma unroll
    for (int i = 0; i < 4; i++)
#pragma unroll
        for (int j = 0; j < 4; j++) acc[i][j] = 0.f;

    const int lr = (tid * 4) >> 4;
    const int lk = (tid * 4) & 15;

    for (int k0 = 0; k0 < K; k0 += 16) {
        {
            const float4 v = *(const float4*)(A + (size_t)(brow + lr) * K + k0 + lk);
            As[lk + 0][lr] = v.x; As[lk + 1][lr] = v.y;
            As[lk + 2][lr] = v.z; As[lk + 3][lr] = v.w;
        }
        {
            float4 v = make_float4(0.f, 0.f, 0.f, 0.f);
            int gcol = bcol + lr;
            if (gcol < N) v = *(const float4*)(W + (size_t)gcol * K + k0 + lk);
            Ws[lk + 0][lr] = v.x; Ws[lk + 1][lr] = v.y;
            Ws[lk + 2][lr] = v.z; Ws[lk + 3][lr] = v.w;
        }
        __syncthreads();
#pragma unroll
        for (int kk = 0; kk < 16; kk++) {
            const float4 av = *(const float4*)&As[kk][ty * 4];
            const float4 wv = *(const float4*)&Ws[kk][tx * 4];
            acc[0][0] += av.x * wv.x; acc[0][1] += av.x * wv.y;
            acc[0][2] += av.x * wv.z; acc[0][3] += av.x * wv.w;
            acc[1][0] += av.y * wv.x; acc[1][1] += av.y * wv.y;
            acc[1][2] += av.y * wv.z; acc[1][3] += av.y * wv.w;
            acc[2][0] += av.z * wv.x; acc[2][1] += av.z * wv.y;
            acc[2][2] += av.z * wv.z; acc[2][3] += av.z * wv.w;
            acc[3][0] += av.w * wv.x; acc[3][1] += av.w * wv.y;
            acc[3][2] += av.w * wv.z; acc[3][3] += av.w * wv.w;
        }
        __syncthreads();
    }

#pragma unroll
    for (int i = 0; i < 4; i++) {
        int row = brow + ty * 4 + i;
#pragma unroll
        for (int j = 0; j < 4; j++) {
            int col = bcol + tx * 4 + j;
            if (col < N) {
                float v = acc[i][j];
                if (bias) v += bias[col];
                if (ACT == 1) v = 0.5f * v * (1.0f + erff(v * 0.70710678118654752f));
                C[(size_t)row * N + col] = v;
            }
        }
    }
}

// ---------------- depthwise causal conv (k=4) + SiLU ----------------
__global__ void conv_silu_kernel(const float* __restrict__ xz, const float* __restrict__ cw,
                                 const float* __restrict__ cb, float* __restrict__ xc) {
    int bv = blockIdx.x;
    int chunk = blockIdx.y;
    int d = threadIdx.x;
    float w0 = cw[d * 4 + 0], w1 = cw[d * 4 + 1], w2 = cw[d * 4 + 2], w3 = cw[d * 4 + 3];
    float bsv = cb[d];
    int t0 = chunk * 64;
    const float* base = xz + ((size_t)bv * SEQ) * (2 * DI) + d;
    float x0 = (t0 - 3 >= 0) ? base[(size_t)(t0 - 3) * (2 * DI)] : 0.f;
    float x1 = (t0 - 2 >= 0) ? base[(size_t)(t0 - 2) * (2 * DI)] : 0.f;
    float x2 = (t0 - 1 >= 0) ? base[(size_t)(t0 - 1) * (2 * DI)] : 0.f;
#pragma unroll 4
    for (int tt = 0; tt < 64; tt++) {
        int t = t0 + tt;
        float x3 = base[(size_t)t * (2 * DI)];
        float v = w0 * x0 + w1 * x1 + w2 * x2 + w3 * x3 + bsv;
        float s = v / (1.0f + __expf(-v));
        xc[((size_t)bv * SEQ + t) * DI + d] = s;
        x0 = x1; x1 = x2; x2 = x3;
    }
}

// ---------------- dt_proj (K=8) + softplus ----------------
__global__ void dt_softplus_kernel(const float* __restrict__ xdbl, const float* __restrict__ dtw,
                                   const float* __restrict__ dtb, float* __restrict__ delta) {
    int row = blockIdx.x;
    int d = threadIdx.x;
    __shared__ float dts[DTR];
    if (d < DTR) dts[d] = xdbl[(size_t)row * 40 + d];
    __syncthreads();
    float acc = dtb[d];
#pragma unroll
    for (int r = 0; r < DTR; r++) acc += dts[r] * dtw[d * DTR + r];
    float sp = (acc > 20.f) ? acc : log1pf(__expf(acc));
    delta[(size_t)row * DI + d] = sp;
}

// ---------------- selective scan (fused +u*D and *silu(z)) ----------------
__global__ void scan_kernel(const float* __restrict__ xc, const float* __restrict__ delta,
                            const float* __restrict__ xdbl, const float* __restrict__ xz,
                            const float* __restrict__ A_log, const float* __restrict__ Dp,
                            float* __restrict__ y) {
    int w = (blockIdx.x * blockDim.x + threadIdx.x) >> 5;
    int lane = threadIdx.x & 31;
    int bv = w >> 7;
    int dp = w & 127;
    int s = lane & 15;
    int d = dp * 2 + (lane >> 4);

    float a = -__expf(A_log[d * DS + s]);
    float Dval = Dp[d];
    float h = 0.f;

    const size_t rbase = (size_t)bv * SEQ;
    for (int t = 0; t < SEQ; t++) {
        size_t rbt = rbase + t;
        float u  = xc[rbt * DI + d];
        float dl = delta[rbt * DI + d];
        float Bv = xdbl[rbt * 40 + DTR + s];
        float Cv = xdbl[rbt * 40 + DTR + DS + s];
        float dA = __expf(dl * a);
        h = dA * h + (dl * u) * Bv;
        float p = h * Cv;
        p += __shfl_xor_sync(0xffffffffu, p, 1, 16);
        p += __shfl_xor_sync(0xffffffffu, p, 2, 16);
        p += __shfl_xor_sync(0xffffffffu, p, 4, 16);
        p += __shfl_xor_sync(0xffffffffu, p, 8, 16);
        if (s == 0) {
            float zv = xz[rbt * (2 * DI) + DI + d];
            float silz = zv / (1.0f + __expf(-zv));
            y[rbt * DI + d] = (p + u * Dval) * silz;
        }
    }
}

// ---------------- final transpose: h[bv,n,dm] -> out[bv,dm,n] ----------------
__global__ void out_transpose_kernel(const float* __restrict__ hbuf, float* __restrict__ out) {
    __shared__ float tile[32][33];
    int bv = blockIdx.x, nc = blockIdx.y, dc = blockIdx.z;
    int tx = threadIdx.x, ty = threadIdx.y;
    tile[ty][tx] = hbuf[((size_t)bv * SEQ + nc * 32 + ty) * DMOD + dc * 32 + tx];
    __syncthreads();
    out[((size_t)bv * DMOD + dc * 32 + ty) * SEQ + nc * 32 + tx] = tile[tx][ty];
}

// ---------------- launch ----------------
extern "C" void kernel_launch(void* const* d_in, const int* in_sizes, int n_in,
                              void* d_out, int out_size) {
    const float* x         = (const float*)d_in[0];
    const float* W_P_w     = (const float*)d_in[1];
    const float* W_P_b     = (const float*)d_in[2];
    const float* in_proj_w = (const float*)d_in[3];
    const float* conv_w    = (const float*)d_in[4];
    const float* conv_b    = (const float*)d_in[5];
    const float* x_proj_w  = (const float*)d_in[6];
    const float* dt_proj_w = (const float*)d_in[7];
    const float* dt_proj_b = (const float*)d_in[8];
    const float* A_log     = (const float*)d_in[9];
    const float* Dp        = (const float*)d_in[10];
    const float* out_proj_w= (const float*)d_in[11];
    const float* lin1_w    = (const float*)d_in[12];
    const float* lin1_b    = (const float*)d_in[13];
    const float* lin2_w    = (const float*)d_in[14];
    const float* lin2_b    = (const float*)d_in[15];
    float* out = (float*)d_out;

    float *hin, *h, *xz, *xc, *xdbl, *delta, *y, *h2, *ff;
    cudaGetSymbolAddress((void**)&hin,   g_hin);
    cudaGetSymbolAddress((void**)&h,     g_h);
    cudaGetSymbolAddress((void**)&xz,    g_xz);
    cudaGetSymbolAddress((void**)&xc,    g_xc);
    cudaGetSymbolAddress((void**)&xdbl,  g_xdbl);
    cudaGetSymbolAddress((void**)&delta, g_delta);
    cudaGetSymbolAddress((void**)&y,     g_y);
    cudaGetSymbolAddress((void**)&h2,    g_h2);
    cudaGetSymbolAddress((void**)&ff,    g_ff);

    const int MT = NROWS / 128;   // 256 row tiles

    patch_transpose_kernel<<<dim3(32, 16), 256>>>(x, hin);
    tgemm_kernel<0><<<dim3(1, MT), 256>>>(hin, W_P_w, W_P_b, h, NROWS, DMOD, PLEN);

    for (int l = 0; l < 2; l++) {
        const float* ipw = in_proj_w  + (size_t)l * (2 * DI) * DMOD;
        const float* cwp = conv_w     + (size_t)l * DI * 4;
        const float* cbp = conv_b     + (size_t)l * DI;
        const float* xpw = x_proj_w   + (size_t)l * 40 * DI;
        const float* dpw = dt_proj_w  + (size_t)l * DI * DTR;
        const float* dpb = dt_proj_b  + (size_t)l * DI;
        const float* alg = A_log      + (size_t)l * DI * DS;
        const float* dvp = Dp         + (size_t)l * DI;
        const float* opw = out_proj_w + (size_t)l * DMOD * DI;
        const float* l1w = lin1_w     + (size_t)l * DFF * DMOD;
        const float* l1b = lin1_b     + (size_t)l * DFF;
        const float* l2w = lin2_w     + (size_t)l * DMOD * DFF;
        const float* l2b = lin2_b     + (size_t)l * DMOD;

        tgemm_kernel<0><<<dim3(4, MT), 256>>>(h, ipw, nullptr, xz, NROWS, 2 * DI, DMOD);
        conv_silu_kernel<<<dim3(32, 16), 256>>>(xz, cwp, cbp, xc);
        sgemm_kernel<0><<<dim3(1, NROWS / 64), 256>>>(xc, xpw, nullptr, xdbl, NROWS, 40, DI);
        dt_softplus_kernel<<<NROWS, 256>>>(xdbl, dpw, dpb, delta);
        scan_kernel<<<1024, 128>>>(xc, delta, xdbl, xz, alg, dvp, y);
        tgemm_kernel<0><<<dim3(1, MT), 256>>>(y, opw, nullptr, h2, NROWS, DMOD, DI);
        tgemm_kernel<1><<<dim3(2, MT), 256>>>(h2, l1w, l1b, ff, NROWS, DFF, DMOD);
        tgemm_kernel<0><<<dim3(1, MT), 256>>>(ff, l2w, l2b, h, NROWS, DMOD, DFF);
    }

    out_transpose_kernel<<<dim3(32, 32, 4), dim3(32, 32)>>>(h, out);
}

// round 4
// speedup vs baseline: 1.7686x; 1.5434x over previous
#include <cuda_runtime.h>
#include <math.h>
#include <stdint.h>

#define BVn   32
#define SEQ   1024
#define DMOD  128
#define DI    256
#define DS    16
#define DFF   256
#define PLEN  16
#define DTR   8
#define NROWS (BVn*SEQ)   // 32768

// ---------------- scratch (static device globals; no allocation) ----------------
__device__ __align__(256) float g_hin[NROWS*PLEN];
__device__ __align__(256) float g_h[NROWS*DMOD];
__device__ __align__(256) float g_xz[NROWS*2*DI];
__device__ __align__(256) float g_xc[NROWS*DI];
__device__ __align__(256) float g_xdbl[NROWS*40];
__device__ __align__(256) float g_delta[NROWS*DI];
__device__ __align__(256) float g_y[NROWS*DI];
__device__ __align__(256) float g_h2[NROWS*DMOD];
__device__ __align__(256) float g_ff[NROWS*DFF];

// ---------------- helpers ----------------
__device__ __forceinline__ uint32_t smem_u32(const void* p) {
    return (uint32_t)__cvta_generic_to_shared(p);
}
__device__ __forceinline__ void cp16(uint32_t s, const void* g) {
    asm volatile("cp.async.cg.shared.global [%0], [%1], 16;" :: "r"(s), "l"(g));
}
__device__ __forceinline__ void cp_commit() {
    asm volatile("cp.async.commit_group;");
}
template<int N>
__device__ __forceinline__ void cp_wait() {
    asm volatile("cp.async.wait_group %0;" :: "n"(N));
}
__device__ __forceinline__ void mma_tf32(float* d, const uint32_t* a, const uint32_t* b) {
    asm volatile(
        "mma.sync.aligned.m16n8k8.row.col.f32.tf32.tf32.f32 "
        "{%0,%1,%2,%3}, {%4,%5,%6,%7}, {%8,%9}, {%0,%1,%2,%3};"
        : "+f"(d[0]), "+f"(d[1]), "+f"(d[2]), "+f"(d[3])
        : "r"(a[0]), "r"(a[1]), "r"(a[2]), "r"(a[3]), "r"(b[0]), "r"(b[1]));
}
__device__ __forceinline__ uint32_t fau(float f) { return __float_as_uint(f); }

#define TG_STRIDE 20   // 16 + 4 pad words; conflict-free fragment access; rows stay 16B-aligned

// ---------------- kernel 1: x (bv,p,n) -> hin (bv*n, p) ----------------
__global__ void patch_transpose_kernel(const float* __restrict__ x, float* __restrict__ hin) {
    __shared__ float tile[PLEN][64 + 1];
    int bv = blockIdx.x;
    int nc = blockIdx.y;
    int tid = threadIdx.x;
    const float* xb = x + (size_t)bv * PLEN * SEQ;
#pragma unroll
    for (int r = 0; r < 4; r++) {
        int idx = r * 256 + tid;
        int p = idx >> 6, nl = idx & 63;
        tile[p][nl] = xb[p * SEQ + nc * 64 + nl];
    }
    __syncthreads();
#pragma unroll
    for (int r = 0; r < 4; r++) {
        int nl = r * 16 + (tid >> 4);
        int p = tid & 15;
        hin[((size_t)bv * SEQ + nc * 64 + nl) * PLEN + p] = tile[p][nl];
    }
}

// ---------------- main tf32 tensor GEMM: 128x128 tile, cp.async double buffer ----------------
// C[M,N] = A[M,K] @ W[N,K]^T (+bias, +GELU). M%128==0, N%128==0, K%16==0.
template<int ACT>
__global__ void __launch_bounds__(256)
tgemm_kernel(const float* __restrict__ A, const float* __restrict__ W,
             const float* __restrict__ bias, float* __restrict__ C,
             int M, int N, int K) {
    __shared__ float As[2][128 * TG_STRIDE];
    __shared__ float Ws[2][128 * TG_STRIDE];

    const int tid  = threadIdx.x;
    const int warp = tid >> 5;
    const int lane = tid & 31;
    const int gid  = lane >> 2;
    const int tig  = lane & 3;
    const int warp_m = warp >> 2;
    const int warp_n = warp & 3;

    const int brow = blockIdx.y << 7;
    const int bcol = blockIdx.x << 7;

    const int l_row = tid >> 1;
    const int l_k0  = (tid & 1) * 8;
    const float* Ag = A + (size_t)(brow + l_row) * K + l_k0;
    const float* Wg = W + (size_t)(bcol + l_row) * K + l_k0;

    uint32_t sA[2], sW[2];
    sA[0] = smem_u32(&As[0][l_row * TG_STRIDE + l_k0]);
    sA[1] = smem_u32(&As[1][l_row * TG_STRIDE + l_k0]);
    sW[0] = smem_u32(&Ws[0][l_row * TG_STRIDE + l_k0]);
    sW[1] = smem_u32(&Ws[1][l_row * TG_STRIDE + l_k0]);

    float acc[4][4][4];
#pragma unroll
    for (int i = 0; i < 4; i++)
#pragma unroll
        for (int j = 0; j < 4; j++)
#pragma unroll
            for (int r = 0; r < 4; r++) acc[i][j][r] = 0.f;

    // stage 0
    cp16(sA[0],      Ag);
    cp16(sA[0] + 16, Ag + 4);
    cp16(sW[0],      Wg);
    cp16(sW[0] + 16, Wg + 4);
    cp_commit();

    const int nk = K >> 4;
    int buf = 0;
    for (int kt = 0; kt < nk; kt++) {
        if (kt + 1 < nk) {
            const float* Ar = Ag + (kt + 1) * 16;
            const float* Wr = Wg + (kt + 1) * 16;
            int nb = buf ^ 1;
            cp16(sA[nb],      Ar);
            cp16(sA[nb] + 16, Ar + 4);
            cp16(sW[nb],      Wr);
            cp16(sW[nb] + 16, Wr + 4);
            cp_commit();
            cp_wait<1>();
        } else {
            cp_wait<0>();
        }
        __syncthreads();

        const float* Ab = As[buf];
        const float* Wb = Ws[buf];
#pragma unroll
        for (int ks = 0; ks < 16; ks += 8) {
            uint32_t afr[4][4];
#pragma unroll
            for (int mf = 0; mf < 4; mf++) {
                int r0 = (warp_m * 64 + mf * 16 + gid) * TG_STRIDE + ks + tig;
                afr[mf][0] = fau(Ab[r0]);
                afr[mf][1] = fau(Ab[r0 + 8 * TG_STRIDE]);
                afr[mf][2] = fau(Ab[r0 + 4]);
                afr[mf][3] = fau(Ab[r0 + 8 * TG_STRIDE + 4]);
            }
            uint32_t bfr[4][2];
#pragma unroll
            for (int nf = 0; nf < 4; nf++) {
                int n0 = (warp_n * 32 + nf * 8 + gid) * TG_STRIDE + ks + tig;
                bfr[nf][0] = fau(Wb[n0]);
                bfr[nf][1] = fau(Wb[n0 + 4]);
            }
#pragma unroll
            for (int mf = 0; mf < 4; mf++)
#pragma unroll
                for (int nf = 0; nf < 4; nf++)
                    mma_tf32(acc[mf][nf], afr[mf], bfr[nf]);
        }
        __syncthreads();
        buf ^= 1;
    }

#pragma unroll
    for (int mf = 0; mf < 4; mf++) {
        int r0 = brow + warp_m * 64 + mf * 16 + gid;
#pragma unroll
        for (int nf = 0; nf < 4; nf++) {
            int c0 = bcol + warp_n * 32 + nf * 8 + tig * 2;
            float b0 = bias ? bias[c0] : 0.f;
            float b1 = bias ? bias[c0 + 1] : 0.f;
            float v0 = acc[mf][nf][0] + b0;
            float v1 = acc[mf][nf][1] + b1;
            float v2 = acc[mf][nf][2] + b0;
            float v3 = acc[mf][nf][3] + b1;
            if (ACT == 1) {
                v0 = 0.5f * v0 * (1.0f + erff(v0 * 0.70710678118654752f));
                v1 = 0.5f * v1 * (1.0f + erff(v1 * 0.70710678118654752f));
                v2 = 0.5f * v2 * (1.0f + erff(v2 * 0.70710678118654752f));
                v3 = 0.5f * v3 * (1.0f + erff(v3 * 0.70710678118654752f));
            }
            *(float2*)(C + (size_t)r0 * N + c0)       = make_float2(v0, v1);
            *(float2*)(C + (size_t)(r0 + 8) * N + c0) = make_float2(v2, v3);
        }
    }
}

// ---------------- narrow tf32 GEMM: 128x64 tile, for x_proj (N=40) ----------------
// W rows clamped to N-1 for loads; epilogue masks cols >= N.
__global__ void __launch_bounds__(256)
tgemm64_kernel(const float* __restrict__ A, const float* __restrict__ W,
               float* __restrict__ C, int M, int N, int K) {
    __shared__ float As[2][128 * TG_STRIDE];
    __shared__ float Ws[2][64 * TG_STRIDE];

    const int tid  = threadIdx.x;
    const int warp = tid >> 5;
    const int lane = tid & 31;
    const int gid  = lane >> 2;
    const int tig  = lane & 3;
    const int warp_m = warp >> 1;   // 0..3 (32 rows)
    const int warp_n = warp & 1;    // 0..1 (32 cols)

    const int brow = blockIdx.y << 7;

    const int l_row = tid >> 1;
    const int l_k0  = (tid & 1) * 8;
    const float* Ag = A + (size_t)(brow + l_row) * K + l_k0;

    const int w_row = tid >> 2;          // 0..63
    const int w_k0  = (tid & 3) * 4;
    int wr = w_row < N ? w_row : N - 1;  // clamp OOB rows
    const float* Wg = W + (size_t)wr * K + w_k0;

    uint32_t sA[2], sW[2];
    sA[0] = smem_u32(&As[0][l_row * TG_STRIDE + l_k0]);
    sA[1] = smem_u32(&As[1][l_row * TG_STRIDE + l_k0]);
    sW[0] = smem_u32(&Ws[0][w_row * TG_STRIDE + w_k0]);
    sW[1] = smem_u32(&Ws[1][w_row * TG_STRIDE + w_k0]);

    float acc[2][4][4];
#pragma unroll
    for (int i = 0; i < 2; i++)
#pragma unroll
        for (int j = 0; j < 4; j++)
#pragma unroll
            for (int r = 0; r < 4; r++) acc[i][j][r] = 0.f;

    cp16(sA[0],      Ag);
    cp16(sA[0] + 16, Ag + 4);
    cp16(sW[0],      Wg);
    cp_commit();

    const int nk = K >> 4;
    int buf = 0;
    for (int kt = 0; kt < nk; kt++) {
        if (kt + 1 < nk) {
            int nb = buf ^ 1;
            const float* Ar = Ag + (kt + 1) * 16;
            cp16(sA[nb],      Ar);
            cp16(sA[nb] + 16, Ar + 4);
            cp16(sW[nb], Wg + (kt + 1) * 16);
            cp_commit();
            cp_wait<1>();
        } else {
            cp_wait<0>();
        }
        __syncthreads();

        const float* Ab = As[buf];
        const float* Wb = Ws[buf];
#pragma unroll
        for (int ks = 0; ks < 16; ks += 8) {
            uint32_t afr[2][4];
#pragma unroll
            for (int mf = 0; mf < 2; mf++) {
                int r0 = (warp_m * 32 + mf * 16 + gid) * TG_STRIDE + ks + tig;
                afr[mf][0] = fau(Ab[r0]);
                afr[mf][1] = fau(Ab[r0 + 8 * TG_STRIDE]);
                afr[mf][2] = fau(Ab[r0 + 4]);
                afr[mf][3] = fau(Ab[r0 + 8 * TG_STRIDE + 4]);
            }
            uint32_t bfr[4][2];
#pragma unroll
            for (int nf = 0; nf < 4; nf++) {
                int n0 = (warp_n * 32 + nf * 8 + gid) * TG_STRIDE + ks + tig;
                bfr[nf][0] = fau(Wb[n0]);
                bfr[nf][1] = fau(Wb[n0 + 4]);
            }
#pragma unroll
            for (int mf = 0; mf < 2; mf++)
#pragma unroll
                for (int nf = 0; nf < 4; nf++)
                    mma_tf32(acc[mf][nf], afr[mf], bfr[nf]);
        }
        __syncthreads();
        buf ^= 1;
    }

#pragma unroll
    for (int mf = 0; mf < 2; mf++) {
        int r0 = brow + warp_m * 32 + mf * 16 + gid;
#pragma unroll
        for (int nf = 0; nf < 4; nf++) {
            int c0 = warp_n * 32 + nf * 8 + tig * 2;
            if (c0 < N) {   // N even, c0 even -> c0+1 < N too
                *(float2*)(C + (size_t)r0 * N + c0) =
                    make_float2(acc[mf][nf][0], acc[mf][nf][1]);
                *(float2*)(C + (size_t)(r0 + 8) * N + c0) =
                    make_float2(acc[mf][nf][2], acc[mf][nf][3]);
            }
        }
    }
}

// ---------------- depthwise causal conv (k=4) + SiLU ----------------
__global__ void conv_silu_kernel(const float* __restrict__ xz, const float* __restrict__ cw,
                                 const float* __restrict__ cb, float* __restrict__ xc) {
    int bv = blockIdx.x;
    int chunk = blockIdx.y;      // 32 chunks of 32 t
    int d = threadIdx.x;
    float w0 = cw[d * 4 + 0], w1 = cw[d * 4 + 1], w2 = cw[d * 4 + 2], w3 = cw[d * 4 + 3];
    float bsv = cb[d];
    int t0 = chunk * 32;
    const float* base = xz + ((size_t)bv * SEQ) * (2 * DI) + d;
    float x0 = (t0 - 3 >= 0) ? base[(size_t)(t0 - 3) * (2 * DI)] : 0.f;
    float x1 = (t0 - 2 >= 0) ? base[(size_t)(t0 - 2) * (2 * DI)] : 0.f;
    float x2 = (t0 - 1 >= 0) ? base[(size_t)(t0 - 1) * (2 * DI)] : 0.f;
#pragma unroll 8
    for (int tt = 0; tt < 32; tt++) {
        int t = t0 + tt;
        float x3 = base[(size_t)t * (2 * DI)];
        float v = w0 * x0 + w1 * x1 + w2 * x2 + w3 * x3 + bsv;
        float s = v / (1.0f + __expf(-v));
        xc[((size_t)bv * SEQ + t) * DI + d] = s;
        x0 = x1; x1 = x2; x2 = x3;
    }
}

// ---------------- dt_proj (K=8) + softplus, 32 rows per block ----------------
__global__ void dt_softplus_kernel(const float* __restrict__ xdbl, const float* __restrict__ dtw,
                                   const float* __restrict__ dtb, float* __restrict__ delta) {
    __shared__ float dts[32][DTR];
    const int r0 = blockIdx.x * 32;
    const int tid = threadIdx.x;
    {
        int r = tid >> 3, c = tid & 7;
        dts[r][c] = xdbl[(size_t)(r0 + r) * 40 + c];
    }
    __syncthreads();
    const int d = tid;
    float w[DTR];
#pragma unroll
    for (int r = 0; r < DTR; r++) w[r] = dtw[d * DTR + r];
    const float b = dtb[d];
#pragma unroll 4
    for (int rr = 0; rr < 32; rr++) {
        float acc = b;
#pragma unroll
        for (int c = 0; c < DTR; c++) acc = fmaf(dts[rr][c], w[c], acc);
        float sp = (acc > 20.f) ? acc : log1pf(__expf(acc));
        delta[(size_t)(r0 + rr) * DI + d] = sp;
    }
}

// ---------------- selective scan (prefetched; fused +u*D and *silu(z)) ----------------
__global__ void scan_kernel(const float* __restrict__ xc, const float* __restrict__ delta,
                            const float* __restrict__ xdbl, const float* __restrict__ xz,
                            const float* __restrict__ A_log, const float* __restrict__ Dp,
                            float* __restrict__ y) {
    int w = (blockIdx.x * blockDim.x + threadIdx.x) >> 5;
    int lane = threadIdx.x & 31;
    int bv = w >> 7;
    int dp = w & 127;
    int s = lane & 15;
    int d = dp * 2 + (lane >> 4);

    float a = -__expf(A_log[d * DS + s]);
    float Dval = Dp[d];
    float h = 0.f;

    const float* pu  = xc    + (size_t)bv * SEQ * DI + d;
    const float* pdl = delta + (size_t)bv * SEQ * DI + d;
    const float* pB  = xdbl  + (size_t)bv * SEQ * 40 + DTR + s;
    const float* pC  = pB + DS;
    const float* pz  = xz    + (size_t)bv * SEQ * (2 * DI) + DI + d;
    float* py        = y     + (size_t)bv * SEQ * DI + d;

    float u_n = *pu, dl_n = *pdl, B_n = *pB, C_n = *pC;

#pragma unroll 2
    for (int t = 0; t < SEQ; t++) {
        float u = u_n, dl = dl_n, Bv = B_n, Cv = C_n;
        if (t + 1 < SEQ) {
            pu += DI; pdl += DI; pB += 40; pC += 40;
            u_n = *pu; dl_n = *pdl; B_n = *pB; C_n = *pC;
        }
        float dA = __expf(dl * a);
        h = fmaf(dA, h, (dl * u) * Bv);
        float p = h * Cv;
        p += __shfl_xor_sync(0xffffffffu, p, 1, 16);
        p += __shfl_xor_sync(0xffffffffu, p, 2, 16);
        p += __shfl_xor_sync(0xffffffffu, p, 4, 16);
        p += __shfl_xor_sync(0xffffffffu, p, 8, 16);
        if (s == 0) {
            float zv = pz[(size_t)t * (2 * DI)];
            float silz = zv / (1.0f + __expf(-zv));
            py[(size_t)t * DI] = (p + u * Dval) * silz;
        }
    }
}

// ---------------- final transpose: h[bv,n,dm] -> out[bv,dm,n] ----------------
__global__ void out_transpose_kernel(const float* __restrict__ hbuf, float* __restrict__ out) {
    __shared__ float tile[32][33];
    int bv = blockIdx.x, nc = blockIdx.y, dc = blockIdx.z;
    int tx = threadIdx.x, ty = threadIdx.y;
    tile[ty][tx] = hbuf[((size_t)bv * SEQ + nc * 32 + ty) * DMOD + dc * 32 + tx];
    __syncthreads();
    out[((size_t)bv * DMOD + dc * 32 + ty) * SEQ + nc * 32 + tx] = tile[tx][ty];
}

// ---------------- launch ----------------
extern "C" void kernel_launch(void* const* d_in, const int* in_sizes, int n_in,
                              void* d_out, int out_size) {
    const float* x         = (const float*)d_in[0];
    const float* W_P_w     = (const float*)d_in[1];
    const float* W_P_b     = (const float*)d_in[2];
    const float* in_proj_w = (const float*)d_in[3];
    const float* conv_w    = (const float*)d_in[4];
    const float* conv_b    = (const float*)d_in[5];
    const float* x_proj_w  = (const float*)d_in[6];
    const float* dt_proj_w = (const float*)d_in[7];
    const float* dt_proj_b = (const float*)d_in[8];
    const float* A_log     = (const float*)d_in[9];
    const float* Dp        = (const float*)d_in[10];
    const float* out_proj_w= (const float*)d_in[11];
    const float* lin1_w    = (const float*)d_in[12];
    const float* lin1_b    = (const float*)d_in[13];
    const float* lin2_w    = (const float*)d_in[14];
    const float* lin2_b    = (const float*)d_in[15];
    float* out = (float*)d_out;

    float *hin, *h, *xz, *xc, *xdbl, *delta, *y, *h2, *ff;
    cudaGetSymbolAddress((void**)&hin,   g_hin);
    cudaGetSymbolAddress((void**)&h,     g_h);
    cudaGetSymbolAddress((void**)&xz,    g_xz);
    cudaGetSymbolAddress((void**)&xc,    g_xc);
    cudaGetSymbolAddress((void**)&xdbl,  g_xdbl);
    cudaGetSymbolAddress((void**)&delta, g_delta);
    cudaGetSymbolAddress((void**)&y,     g_y);
    cudaGetSymbolAddress((void**)&h2,    g_h2);
    cudaGetSymbolAddress((void**)&ff,    g_ff);

    const int MT = NROWS / 128;   // 256 row tiles

    patch_transpose_kernel<<<dim3(32, 16), 256>>>(x, hin);
    tgemm_kernel<0><<<dim3(1, MT), 256>>>(hin, W_P_w, W_P_b, h, NROWS, DMOD, PLEN);

    for (int l = 0; l < 2; l++) {
        const float* ipw = in_proj_w  + (size_t)l * (2 * DI) * DMOD;
        const float* cwp = conv_w     + (size_t)l * DI * 4;
        const float* cbp = conv_b     + (size_t)l * DI;
        const float* xpw = x_proj_w   + (size_t)l * 40 * DI;
        const float* dpw = dt_proj_w  + (size_t)l * DI * DTR;
        const float* dpb = dt_proj_b  + (size_t)l * DI;
        const float* alg = A_log      + (size_t)l * DI * DS;
        const float* dvp = Dp         + (size_t)l * DI;
        const float* opw = out_proj_w + (size_t)l * DMOD * DI;
        const float* l1w = lin1_w     + (size_t)l * DFF * DMOD;
        const float* l1b = lin1_b     + (size_t)l * DFF;
        const float* l2w = lin2_w     + (size_t)l * DMOD * DFF;
        const float* l2b = lin2_b     + (size_t)l * DMOD;

        tgemm_kernel<0><<<dim3(4, MT), 256>>>(h, ipw, nullptr, xz, NROWS, 2 * DI, DMOD);
        conv_silu_kernel<<<dim3(32, 32), 256>>>(xz, cwp, cbp, xc);
        tgemm64_kernel<<<dim3(1, MT), 256>>>(xc, xpw, xdbl, NROWS, 40, DI);
        dt_softplus_kernel<<<NROWS / 32, 256>>>(xdbl, dpw, dpb, delta);
        scan_kernel<<<1024, 128>>>(xc, delta, xdbl, xz, alg, dvp, y);
        tgemm_kernel<0><<<dim3(1, MT), 256>>>(y, opw, nullptr, h2, NROWS, DMOD, DI);
        tgemm_kernel<1><<<dim3(2, MT), 256>>>(h2, l1w, l1b, ff, NROWS, DFF, DMOD);
        tgemm_kernel<0><<<dim3(1, MT), 256>>>(ff, l2w, l2b, h, NROWS, DMOD, DFF);
    }

    out_transpose_kernel<<<dim3(32, 32, 4), dim3(32, 32)>>>(h, out);
}

// round 5
// speedup vs baseline: 1.7716x; 1.0017x over previous
#include <cuda_runtime.h>
#include <math.h>
#include <stdint.h>

#define BVn   32
#define SEQ   1024
#define DMOD  128
#define DI    256
#define DS    16
#define DFF   256
#define PLEN  16
#define DTR   8
#define NROWS (BVn*SEQ)   // 32768

// ---------------- scratch (static device globals; no allocation) ----------------
__device__ __align__(256) float g_hin[NROWS*PLEN];
__device__ __align__(256) float g_h[NROWS*DMOD];
__device__ __align__(256) float g_xz[NROWS*2*DI];
__device__ __align__(256) float g_xc[NROWS*DI];
__device__ __align__(256) float g_xdbl[NROWS*40];
__device__ __align__(256) float g_delta[NROWS*DI];
__device__ __align__(256) float g_y[NROWS*DI];
__device__ __align__(256) float g_h2[NROWS*DMOD];
__device__ __align__(256) float g_ff[NROWS*DFF];

// ---------------- helpers ----------------
__device__ __forceinline__ uint32_t smem_u32(const void* p) {
    return (uint32_t)__cvta_generic_to_shared(p);
}
__device__ __forceinline__ void cp16(uint32_t s, const void* g) {
    asm volatile("cp.async.cg.shared.global [%0], [%1], 16;" :: "r"(s), "l"(g));
}
__device__ __forceinline__ void cp_commit() {
    asm volatile("cp.async.commit_group;");
}
template<int N>
__device__ __forceinline__ void cp_wait() {
    asm volatile("cp.async.wait_group %0;" :: "n"(N));
}
__device__ __forceinline__ void mma_tf32(float* d, const uint32_t* a, const uint32_t* b) {
    asm volatile(
        "mma.sync.aligned.m16n8k8.row.col.f32.tf32.tf32.f32 "
        "{%0,%1,%2,%3}, {%4,%5,%6,%7}, {%8,%9}, {%0,%1,%2,%3};"
        : "+f"(d[0]), "+f"(d[1]), "+f"(d[2]), "+f"(d[3])
        : "r"(a[0]), "r"(a[1]), "r"(a[2]), "r"(a[3]), "r"(b[0]), "r"(b[1]));
}
__device__ __forceinline__ uint32_t fau(float f) { return __float_as_uint(f); }

#define TG_STRIDE 20            // 16 + 4 pad words; conflict-free; rows 16B-aligned
#define TG_ST     (128 * TG_STRIDE)
#define TG_SMEM_BYTES (6 * TG_ST * 4)   // 3 stages x (A + W) = 61440 B

// ---------------- kernel 1: x (bv,p,n) -> hin (bv*n, p) ----------------
__global__ void patch_transpose_kernel(const float* __restrict__ x, float* __restrict__ hin) {
    __shared__ float tile[PLEN][64 + 1];
    int bv = blockIdx.x;
    int nc = blockIdx.y;
    int tid = threadIdx.x;
    const float* xb = x + (size_t)bv * PLEN * SEQ;
#pragma unroll
    for (int r = 0; r < 4; r++) {
        int idx = r * 256 + tid;
        int p = idx >> 6, nl = idx & 63;
        tile[p][nl] = xb[p * SEQ + nc * 64 + nl];
    }
    __syncthreads();
#pragma unroll
    for (int r = 0; r < 4; r++) {
        int nl = r * 16 + (tid >> 4);
        int p = tid & 15;
        hin[((size_t)bv * SEQ + nc * 64 + nl) * PLEN + p] = tile[p][nl];
    }
}

// ---------------- main tf32 tensor GEMM: 128x128 tile, 3-stage cp.async ring ----------------
// C[M,N] = A[M,K] @ W[N,K]^T (+bias, +GELU). M%128==0, N%128==0, K%16==0.
template<int ACT>
__global__ void __launch_bounds__(256)
tgemm_kernel(const float* __restrict__ A, const float* __restrict__ W,
             const float* __restrict__ bias, float* __restrict__ C,
             int M, int N, int K) {
    extern __shared__ float dsm[];
    float* Asm = dsm;               // 3 stages of 128*TG_STRIDE
    float* Wsm = dsm + 3 * TG_ST;

    const int tid  = threadIdx.x;
    const int warp = tid >> 5;
    const int lane = tid & 31;
    const int gid  = lane >> 2;
    const int tig  = lane & 3;
    const int warp_m = warp >> 2;
    const int warp_n = warp & 3;

    const int brow = blockIdx.y << 7;
    const int bcol = blockIdx.x << 7;

    const int l_row = tid >> 1;
    const int l_k0  = (tid & 1) * 8;
    const float* Ag = A + (size_t)(brow + l_row) * K + l_k0;
    const float* Wg = W + (size_t)(bcol + l_row) * K + l_k0;

    uint32_t sA[3], sW[3];
#pragma unroll
    for (int s = 0; s < 3; s++) {
        sA[s] = smem_u32(&Asm[s * TG_ST + l_row * TG_STRIDE + l_k0]);
        sW[s] = smem_u32(&Wsm[s * TG_ST + l_row * TG_STRIDE + l_k0]);
    }

    float acc[4][4][4];
#pragma unroll
    for (int i = 0; i < 4; i++)
#pragma unroll
        for (int j = 0; j < 4; j++)
#pragma unroll
            for (int r = 0; r < 4; r++) acc[i][j][r] = 0.f;

    const int nk = K >> 4;

    // prologue: stages 0,1
#pragma unroll
    for (int s = 0; s < 2; s++) {
        if (s < nk) {
            const float* Ar = Ag + s * 16;
            const float* Wr = Wg + s * 16;
            cp16(sA[s],      Ar);
            cp16(sA[s] + 16, Ar + 4);
            cp16(sW[s],      Wr);
            cp16(sW[s] + 16, Wr + 4);
        }
        cp_commit();
    }

    int stage = 0;
    for (int kt = 0; kt < nk; kt++) {
        cp_wait<1>();
        __syncthreads();

        // prefetch kt+2 into (stage+2)%3  (slot last computed at kt-1; barrier above protects it)
        int ns = stage + 2; if (ns >= 3) ns -= 3;
        if (kt + 2 < nk) {
            const float* Ar = Ag + (kt + 2) * 16;
            const float* Wr = Wg + (kt + 2) * 16;
            cp16(sA[ns],      Ar);
            cp16(sA[ns] + 16, Ar + 4);
            cp16(sW[ns],      Wr);
            cp16(sW[ns] + 16, Wr + 4);
        }
        cp_commit();

        const float* Ab = Asm + stage * TG_ST;
        const float* Wb = Wsm + stage * TG_ST;
#pragma unroll
        for (int ks = 0; ks < 16; ks += 8) {
            uint32_t afr[4][4];
#pragma unroll
            for (int mf = 0; mf < 4; mf++) {
                int r0 = (warp_m * 64 + mf * 16 + gid) * TG_STRIDE + ks + tig;
                afr[mf][0] = fau(Ab[r0]);
                afr[mf][1] = fau(Ab[r0 + 8 * TG_STRIDE]);
                afr[mf][2] = fau(Ab[r0 + 4]);
                afr[mf][3] = fau(Ab[r0 + 8 * TG_STRIDE + 4]);
            }
            uint32_t bfr[4][2];
#pragma unroll
            for (int nf = 0; nf < 4; nf++) {
                int n0 = (warp_n * 32 + nf * 8 + gid) * TG_STRIDE + ks + tig;
                bfr[nf][0] = fau(Wb[n0]);
                bfr[nf][1] = fau(Wb[n0 + 4]);
            }
#pragma unroll
            for (int mf = 0; mf < 4; mf++)
#pragma unroll
                for (int nf = 0; nf < 4; nf++)
                    mma_tf32(acc[mf][nf], afr[mf], bfr[nf]);
        }

        stage++; if (stage == 3) stage = 0;
    }

#pragma unroll
    for (int mf = 0; mf < 4; mf++) {
        int r0 = brow + warp_m * 64 + mf * 16 + gid;
#pragma unroll
        for (int nf = 0; nf < 4; nf++) {
            int c0 = bcol + warp_n * 32 + nf * 8 + tig * 2;
            float b0 = bias ? bias[c0] : 0.f;
            float b1 = bias ? bias[c0 + 1] : 0.f;
            float v0 = acc[mf][nf][0] + b0;
            float v1 = acc[mf][nf][1] + b1;
            float v2 = acc[mf][nf][2] + b0;
            float v3 = acc[mf][nf][3] + b1;
            if (ACT == 1) {
                v0 = 0.5f * v0 * (1.0f + erff(v0 * 0.70710678118654752f));
                v1 = 0.5f * v1 * (1.0f + erff(v1 * 0.70710678118654752f));
                v2 = 0.5f * v2 * (1.0f + erff(v2 * 0.70710678118654752f));
                v3 = 0.5f * v3 * (1.0f + erff(v3 * 0.70710678118654752f));
            }
            *(float2*)(C + (size_t)r0 * N + c0)       = make_float2(v0, v1);
            *(float2*)(C + (size_t)(r0 + 8) * N + c0) = make_float2(v2, v3);
        }
    }
}

// ---------------- narrow tf32 GEMM: 128x64 tile, 3-stage ring, for x_proj (N=40) ----------------
__global__ void __launch_bounds__(256)
tgemm64_kernel(const float* __restrict__ A, const float* __restrict__ W,
               float* __restrict__ C, int M, int N, int K) {
    __shared__ float Asm[3][128 * TG_STRIDE];
    __shared__ float Wsm[3][64 * TG_STRIDE];

    const int tid  = threadIdx.x;
    const int warp = tid >> 5;
    const int lane = tid & 31;
    const int gid  = lane >> 2;
    const int tig  = lane & 3;
    const int warp_m = warp >> 1;   // 0..3
    const int warp_n = warp & 1;    // 0..1

    const int brow = blockIdx.y << 7;

    const int l_row = tid >> 1;
    const int l_k0  = (tid & 1) * 8;
    const float* Ag = A + (size_t)(brow + l_row) * K + l_k0;

    const int w_row = tid >> 2;
    const int w_k0  = (tid & 3) * 4;
    int wr = w_row < N ? w_row : N - 1;
    const float* Wg = W + (size_t)wr * K + w_k0;

    uint32_t sA[3], sW[3];
#pragma unroll
    for (int s = 0; s < 3; s++) {
        sA[s] = smem_u32(&Asm[s][l_row * TG_STRIDE + l_k0]);
        sW[s] = smem_u32(&Wsm[s][w_row * TG_STRIDE + w_k0]);
    }

    float acc[2][4][4];
#pragma unroll
    for (int i = 0; i < 2; i++)
#pragma unroll
        for (int j = 0; j < 4; j++)
#pragma unroll
            for (int r = 0; r < 4; r++) acc[i][j][r] = 0.f;

    const int nk = K >> 4;
#pragma unroll
    for (int s = 0; s < 2; s++) {
        if (s < nk) {
            const float* Ar = Ag + s * 16;
            cp16(sA[s],      Ar);
            cp16(sA[s] + 16, Ar + 4);
            cp16(sW[s], Wg + s * 16);
        }
        cp_commit();
    }

    int stage = 0;
    for (int kt = 0; kt < nk; kt++) {
        cp_wait<1>();
        __syncthreads();

        int ns = stage + 2; if (ns >= 3) ns -= 3;
        if (kt + 2 < nk) {
            const float* Ar = Ag + (kt + 2) * 16;
            cp16(sA[ns],      Ar);
            cp16(sA[ns] + 16, Ar + 4);
            cp16(sW[ns], Wg + (kt + 2) * 16);
        }
        cp_commit();

        const float* Ab = Asm[stage];
        const float* Wb = Wsm[stage];
#pragma unroll
        for (int ks = 0; ks < 16; ks += 8) {
            uint32_t afr[2][4];
#pragma unroll
            for (int mf = 0; mf < 2; mf++) {
                int r0 = (warp_m * 32 + mf * 16 + gid) * TG_STRIDE + ks + tig;
                afr[mf][0] = fau(Ab[r0]);
                afr[mf][1] = fau(Ab[r0 + 8 * TG_STRIDE]);
                afr[mf][2] = fau(Ab[r0 + 4]);
                afr[mf][3] = fau(Ab[r0 + 8 * TG_STRIDE + 4]);
            }
            uint32_t bfr[4][2];
#pragma unroll
            for (int nf = 0; nf < 4; nf++) {
                int n0 = (warp_n * 32 + nf * 8 + gid) * TG_STRIDE + ks + tig;
                bfr[nf][0] = fau(Wb[n0]);
                bfr[nf][1] = fau(Wb[n0 + 4]);
            }
#pragma unroll
            for (int mf = 0; mf < 2; mf++)
#pragma unroll
                for (int nf = 0; nf < 4; nf++)
                    mma_tf32(acc[mf][nf], afr[mf], bfr[nf]);
        }

        stage++; if (stage == 3) stage = 0;
    }

#pragma unroll
    for (int mf = 0; mf < 2; mf++) {
        int r0 = brow + warp_m * 32 + mf * 16 + gid;
#pragma unroll
        for (int nf = 0; nf < 4; nf++) {
            int c0 = warp_n * 32 + nf * 8 + tig * 2;
            if (c0 < N) {
                *(float2*)(C + (size_t)r0 * N + c0) =
                    make_float2(acc[mf][nf][0], acc[mf][nf][1]);
                *(float2*)(C + (size_t)(r0 + 8) * N + c0) =
                    make_float2(acc[mf][nf][2], acc[mf][nf][3]);
            }
        }
    }
}

// ---------------- depthwise causal conv (k=4) + SiLU ----------------
__global__ void conv_silu_kernel(const float* __restrict__ xz, const float* __restrict__ cw,
                                 const float* __restrict__ cb, float* __restrict__ xc) {
    int bv = blockIdx.x;
    int chunk = blockIdx.y;      // 32 chunks of 32 t
    int d = threadIdx.x;
    float w0 = cw[d * 4 + 0], w1 = cw[d * 4 + 1], w2 = cw[d * 4 + 2], w3 = cw[d * 4 + 3];
    float bsv = cb[d];
    int t0 = chunk * 32;
    const float* base = xz + ((size_t)bv * SEQ) * (2 * DI) + d;
    float x0 = (t0 - 3 >= 0) ? base[(size_t)(t0 - 3) * (2 * DI)] : 0.f;
    float x1 = (t0 - 2 >= 0) ? base[(size_t)(t0 - 2) * (2 * DI)] : 0.f;
    float x2 = (t0 - 1 >= 0) ? base[(size_t)(t0 - 1) * (2 * DI)] : 0.f;
#pragma unroll 8
    for (int tt = 0; tt < 32; tt++) {
        int t = t0 + tt;
        float x3 = base[(size_t)t * (2 * DI)];
        float v = w0 * x0 + w1 * x1 + w2 * x2 + w3 * x3 + bsv;
        float s = v / (1.0f + __expf(-v));
        xc[((size_t)bv * SEQ + t) * DI + d] = s;
        x0 = x1; x1 = x2; x2 = x3;
    }
}

// ---------------- dt_proj (K=8) + softplus, 32 rows per block ----------------
__global__ void dt_softplus_kernel(const float* __restrict__ xdbl, const float* __restrict__ dtw,
                                   const float* __restrict__ dtb, float* __restrict__ delta) {
    __shared__ float dts[32][DTR];
    const int r0 = blockIdx.x * 32;
    const int tid = threadIdx.x;
    {
        int r = tid >> 3, c = tid & 7;
        dts[r][c] = xdbl[(size_t)(r0 + r) * 40 + c];
    }
    __syncthreads();
    const int d = tid;
    float w[DTR];
#pragma unroll
    for (int r = 0; r < DTR; r++) w[r] = dtw[d * DTR + r];
    const float b = dtb[d];
#pragma unroll 4
    for (int rr = 0; rr < 32; rr++) {
        float acc = b;
#pragma unroll
        for (int c = 0; c < DTR; c++) acc = fmaf(dts[rr][c], w[c], acc);
        float sp = (acc > 20.f) ? acc : log1pf(__expf(acc));
        delta[(size_t)(r0 + rr) * DI + d] = sp;
    }
}

// ---------------- selective scan (prefetched; fused +u*D and *silu(z)) ----------------
__global__ void scan_kernel(const float* __restrict__ xc, const float* __restrict__ delta,
                            const float* __restrict__ xdbl, const float* __restrict__ xz,
                            const float* __restrict__ A_log, const float* __restrict__ Dp,
                            float* __restrict__ y) {
    int w = (blockIdx.x * blockDim.x + threadIdx.x) >> 5;
    int lane = threadIdx.x & 31;
    int bv = w >> 7;
    int dp = w & 127;
    int s = lane & 15;
    int d = dp * 2 + (lane >> 4);

    float a = -__expf(A_log[d * DS + s]);
    float Dval = Dp[d];
    float h = 0.f;

    const float* pu  = xc    + (size_t)bv * SEQ * DI + d;
    const float* pdl = delta + (size_t)bv * SEQ * DI + d;
    const float* pB  = xdbl  + (size_t)bv * SEQ * 40 + DTR + s;
    const float* pC  = pB + DS;
    const float* pz  = xz    + (size_t)bv * SEQ * (2 * DI) + DI + d;
    float* py        = y     + (size_t)bv * SEQ * DI + d;

    float u_n = *pu, dl_n = *pdl, B_n = *pB, C_n = *pC;

#pragma unroll 2
    for (int t = 0; t < SEQ; t++) {
        float u = u_n, dl = dl_n, Bv = B_n, Cv = C_n;
        if (t + 1 < SEQ) {
            pu += DI; pdl += DI; pB += 40; pC += 40;
            u_n = *pu; dl_n = *pdl; B_n = *pB; C_n = *pC;
        }
        float dA = __expf(dl * a);
        h = fmaf(dA, h, (dl * u) * Bv);
        float p = h * Cv;
        p += __shfl_xor_sync(0xffffffffu, p, 1, 16);
        p += __shfl_xor_sync(0xffffffffu, p, 2, 16);
        p += __shfl_xor_sync(0xffffffffu, p, 4, 16);
        p += __shfl_xor_sync(0xffffffffu, p, 8, 16);
        if (s == 0) {
            float zv = pz[(size_t)t * (2 * DI)];
            float silz = zv / (1.0f + __expf(-zv));
            py[(size_t)t * DI] = (p + u * Dval) * silz;
        }
    }
}

// ---------------- final transpose: h[bv,n,dm] -> out[bv,dm,n] ----------------
__global__ void out_transpose_kernel(const float* __restrict__ hbuf, float* __restrict__ out) {
    __shared__ float tile[32][33];
    int bv = blockIdx.x, nc = blockIdx.y, dc = blockIdx.z;
    int tx = threadIdx.x, ty = threadIdx.y;
    tile[ty][tx] = hbuf[((size_t)bv * SEQ + nc * 32 + ty) * DMOD + dc * 32 + tx];
    __syncthreads();
    out[((size_t)bv * DMOD + dc * 32 + ty) * SEQ + nc * 32 + tx] = tile[tx][ty];
}

// ---------------- launch ----------------
extern "C" void kernel_launch(void* const* d_in, const int* in_sizes, int n_in,
                              void* d_out, int out_size) {
    const float* x         = (const float*)d_in[0];
    const float* W_P_w     = (const float*)d_in[1];
    const float* W_P_b     = (const float*)d_in[2];
    const float* in_proj_w = (const float*)d_in[3];
    const float* conv_w    = (const float*)d_in[4];
    const float* conv_b    = (const float*)d_in[5];
    const float* x_proj_w  = (const float*)d_in[6];
    const float* dt_proj_w = (const float*)d_in[7];
    const float* dt_proj_b = (const float*)d_in[8];
    const float* A_log     = (const float*)d_in[9];
    const float* Dp        = (const float*)d_in[10];
    const float* out_proj_w= (const float*)d_in[11];
    const float* lin1_w    = (const float*)d_in[12];
    const float* lin1_b    = (const float*)d_in[13];
    const float* lin2_w    = (const float*)d_in[14];
    const float* lin2_b    = (const float*)d_in[15];
    float* out = (float*)d_out;

    float *hin, *h, *xz, *xc, *xdbl, *delta, *y, *h2, *ff;
    cudaGetSymbolAddress((void**)&hin,   g_hin);
    cudaGetSymbolAddress((void**)&h,     g_h);
    cudaGetSymbolAddress((void**)&xz,    g_xz);
    cudaGetSymbolAddress((void**)&xc,    g_xc);
    cudaGetSymbolAddress((void**)&xdbl,  g_xdbl);
    cudaGetSymbolAddress((void**)&delta, g_delta);
    cudaGetSymbolAddress((void**)&y,     g_y);
    cudaGetSymbolAddress((void**)&h2,    g_h2);
    cudaGetSymbolAddress((void**)&ff,    g_ff);

    static bool attr_done = false;
    if (!attr_done) {
        cudaFuncSetAttribute(tgemm_kernel<0>, cudaFuncAttributeMaxDynamicSharedMemorySize, TG_SMEM_BYTES);
        cudaFuncSetAttribute(tgemm_kernel<1>, cudaFuncAttributeMaxDynamicSharedMemorySize, TG_SMEM_BYTES);
        attr_done = true;
    }

    const int MT = NROWS / 128;   // 256 row tiles

    patch_transpose_kernel<<<dim3(32, 16), 256>>>(x, hin);
    tgemm_kernel<0><<<dim3(1, MT), 256, TG_SMEM_BYTES>>>(hin, W_P_w, W_P_b, h, NROWS, DMOD, PLEN);

    for (int l = 0; l < 2; l++) {
        const float* ipw = in_proj_w  + (size_t)l * (2 * DI) * DMOD;
        const float* cwp = conv_w     + (size_t)l * DI * 4;
        const float* cbp = conv_b     + (size_t)l * DI;
        const float* xpw = x_proj_w   + (size_t)l * 40 * DI;
        const float* dpw = dt_proj_w  + (size_t)l * DI * DTR;
        const float* dpb = dt_proj_b  + (size_t)l * DI;
        const float* alg = A_log      + (size_t)l * DI * DS;
        const float* dvp = Dp         + (size_t)l * DI;
        const float* opw = out_proj_w + (size_t)l * DMOD * DI;
        const float* l1w = lin1_w     + (size_t)l * DFF * DMOD;
        const float* l1b = lin1_b     + (size_t)l * DFF;
        const float* l2w = lin2_w     + (size_t)l * DMOD * DFF;
        const float* l2b = lin2_b     + (size_t)l * DMOD;

        tgemm_kernel<0><<<dim3(4, MT), 256, TG_SMEM_BYTES>>>(h, ipw, nullptr, xz, NROWS, 2 * DI, DMOD);
        conv_silu_kernel<<<dim3(32, 32), 256>>>(xz, cwp, cbp, xc);
        tgemm64_kernel<<<dim3(1, MT), 256>>>(xc, xpw, xdbl, NROWS, 40, DI);
        dt_softplus_kernel<<<NROWS / 32, 256>>>(xdbl, dpw, dpb, delta);
        scan_kernel<<<1024, 128>>>(xc, delta, xdbl, xz, alg, dvp, y);
        tgemm_kernel<0><<<dim3(1, MT), 256, TG_SMEM_BYTES>>>(y, opw, nullptr, h2, NROWS, DMOD, DI);
        tgemm_kernel<1><<<dim3(2, MT), 256, TG_SMEM_BYTES>>>(h2, l1w, l1b, ff, NROWS, DFF, DMOD);
        tgemm_kernel<0><<<dim3(1, MT), 256, TG_SMEM_BYTES>>>(ff, l2w, l2b, h, NROWS, DMOD, DFF);
    }

    out_transpose_kernel<<<dim3(32, 32, 4), dim3(32, 32)>>>(h, out);
}

// round 6
// speedup vs baseline: 2.6424x; 1.4915x over previous
#include <cuda_runtime.h>
#include <math.h>
#include <stdint.h>

#define BVn   32
#define SEQ   1024
#define DMOD  128
#define DI    256
#define DS    16
#define DFF   256
#define PLEN  16
#define DTR   8
#define NROWS (BVn*SEQ)   // 32768

// ---------------- scratch (static device globals; no allocation) ----------------
__device__ __align__(256) float g_hin[NROWS*PLEN];
__device__ __align__(256) float g_h[NROWS*DMOD];
__device__ __align__(256) float g_xz[NROWS*2*DI];
__device__ __align__(256) float g_xc[NROWS*DI];
__device__ __align__(256) float g_xdbl[NROWS*40];
__device__ __align__(256) float g_delta[NROWS*DI];
__device__ __align__(256) float g_y[NROWS*DI];
__device__ __align__(256) float g_h2[NROWS*DMOD];
__device__ __align__(256) float g_ff[NROWS*DFF];

// ---------------- helpers ----------------
__device__ __forceinline__ uint32_t smem_u32(const void* p) {
    return (uint32_t)__cvta_generic_to_shared(p);
}
__device__ __forceinline__ void cp16(uint32_t s, const void* g) {
    asm volatile("cp.async.cg.shared.global [%0], [%1], 16;" :: "r"(s), "l"(g));
}
__device__ __forceinline__ void cp_commit() {
    asm volatile("cp.async.commit_group;");
}
template<int N>
__device__ __forceinline__ void cp_wait() {
    asm volatile("cp.async.wait_group %0;" :: "n"(N));
}
__device__ __forceinline__ void mma_tf32(float* d, const uint32_t* a, const uint32_t* b) {
    asm volatile(
        "mma.sync.aligned.m16n8k8.row.col.f32.tf32.tf32.f32 "
        "{%0,%1,%2,%3}, {%4,%5,%6,%7}, {%8,%9}, {%0,%1,%2,%3};"
        : "+f"(d[0]), "+f"(d[1]), "+f"(d[2]), "+f"(d[3])
        : "r"(a[0]), "r"(a[1]), "r"(a[2]), "r"(a[3]), "r"(b[0]), "r"(b[1]));
}
__device__ __forceinline__ uint32_t fau(float f) { return __float_as_uint(f); }

#define TG_STRIDE 20            // 16 + 4 pad words; conflict-free; rows 16B-aligned
#define TG_ST     (128 * TG_STRIDE)
#define TG_SMEM_BYTES (6 * TG_ST * 4)   // 3 stages x (A + W) = 61440 B

// ---------------- kernel 1: x (bv,p,n) -> hin (bv*n, p) ----------------
__global__ void patch_transpose_kernel(const float* __restrict__ x, float* __restrict__ hin) {
    __shared__ float tile[PLEN][64 + 1];
    int bv = blockIdx.x;
    int nc = blockIdx.y;
    int tid = threadIdx.x;
    const float* xb = x + (size_t)bv * PLEN * SEQ;
#pragma unroll
    for (int r = 0; r < 4; r++) {
        int idx = r * 256 + tid;
        int p = idx >> 6, nl = idx & 63;
        tile[p][nl] = xb[p * SEQ + nc * 64 + nl];
    }
    __syncthreads();
#pragma unroll
    for (int r = 0; r < 4; r++) {
        int nl = r * 16 + (tid >> 4);
        int p = tid & 15;
        hin[((size_t)bv * SEQ + nc * 64 + nl) * PLEN + p] = tile[p][nl];
    }
}

// ---------------- main tf32 tensor GEMM: 128x128 tile, 3-stage cp.async ring ----------------
template<int ACT>
__global__ void __launch_bounds__(256)
tgemm_kernel(const float* __restrict__ A, const float* __restrict__ W,
             const float* __restrict__ bias, float* __restrict__ C,
             int M, int N, int K) {
    extern __shared__ float dsm[];
    float* Asm = dsm;
    float* Wsm = dsm + 3 * TG_ST;

    const int tid  = threadIdx.x;
    const int warp = tid >> 5;
    const int lane = tid & 31;
    const int gid  = lane >> 2;
    const int tig  = lane & 3;
    const int warp_m = warp >> 2;
    const int warp_n = warp & 3;

    const int brow = blockIdx.y << 7;
    const int bcol = blockIdx.x << 7;

    const int l_row = tid >> 1;
    const int l_k0  = (tid & 1) * 8;
    const float* Ag = A + (size_t)(brow + l_row) * K + l_k0;
    const float* Wg = W + (size_t)(bcol + l_row) * K + l_k0;

    uint32_t sA[3], sW[3];
#pragma unroll
    for (int s = 0; s < 3; s++) {
        sA[s] = smem_u32(&Asm[s * TG_ST + l_row * TG_STRIDE + l_k0]);
        sW[s] = smem_u32(&Wsm[s * TG_ST + l_row * TG_STRIDE + l_k0]);
    }

    float acc[4][4][4];
#pragma unroll
    for (int i = 0; i < 4; i++)
#pragma unroll
        for (int j = 0; j < 4; j++)
#pragma unroll
            for (int r = 0; r < 4; r++) acc[i][j][r] = 0.f;

    const int nk = K >> 4;

#pragma unroll
    for (int s = 0; s < 2; s++) {
        if (s < nk) {
            const float* Ar = Ag + s * 16;
            const float* Wr = Wg + s * 16;
            cp16(sA[s],      Ar);
            cp16(sA[s] + 16, Ar + 4);
            cp16(sW[s],      Wr);
            cp16(sW[s] + 16, Wr + 4);
        }
        cp_commit();
    }

    int stage = 0;
    for (int kt = 0; kt < nk; kt++) {
        cp_wait<1>();
        __syncthreads();

        int ns = stage + 2; if (ns >= 3) ns -= 3;
        if (kt + 2 < nk) {
            const float* Ar = Ag + (kt + 2) * 16;
            const float* Wr = Wg + (kt + 2) * 16;
            cp16(sA[ns],      Ar);
            cp16(sA[ns] + 16, Ar + 4);
            cp16(sW[ns],      Wr);
            cp16(sW[ns] + 16, Wr + 4);
        }
        cp_commit();

        const float* Ab = Asm + stage * TG_ST;
        const float* Wb = Wsm + stage * TG_ST;
#pragma unroll
        for (int ks = 0; ks < 16; ks += 8) {
            uint32_t afr[4][4];
#pragma unroll
            for (int mf = 0; mf < 4; mf++) {
                int r0 = (warp_m * 64 + mf * 16 + gid) * TG_STRIDE + ks + tig;
                afr[mf][0] = fau(Ab[r0]);
                afr[mf][1] = fau(Ab[r0 + 8 * TG_STRIDE]);
                afr[mf][2] = fau(Ab[r0 + 4]);
                afr[mf][3] = fau(Ab[r0 + 8 * TG_STRIDE + 4]);
            }
            uint32_t bfr[4][2];
#pragma unroll
            for (int nf = 0; nf < 4; nf++) {
                int n0 = (warp_n * 32 + nf * 8 + gid) * TG_STRIDE + ks + tig;
                bfr[nf][0] = fau(Wb[n0]);
                bfr[nf][1] = fau(Wb[n0 + 4]);
            }
#pragma unroll
            for (int mf = 0; mf < 4; mf++)
#pragma unroll
                for (int nf = 0; nf < 4; nf++)
                    mma_tf32(acc[mf][nf], afr[mf], bfr[nf]);
        }

        stage++; if (stage == 3) stage = 0;
    }

#pragma unroll
    for (int mf = 0; mf < 4; mf++) {
        int r0 = brow + warp_m * 64 + mf * 16 + gid;
#pragma unroll
        for (int nf = 0; nf < 4; nf++) {
            int c0 = bcol + warp_n * 32 + nf * 8 + tig * 2;
            float b0 = bias ? bias[c0] : 0.f;
            float b1 = bias ? bias[c0 + 1] : 0.f;
            float v0 = acc[mf][nf][0] + b0;
            float v1 = acc[mf][nf][1] + b1;
            float v2 = acc[mf][nf][2] + b0;
            float v3 = acc[mf][nf][3] + b1;
            if (ACT == 1) {
                v0 = 0.5f * v0 * (1.0f + erff(v0 * 0.70710678118654752f));
                v1 = 0.5f * v1 * (1.0f + erff(v1 * 0.70710678118654752f));
                v2 = 0.5f * v2 * (1.0f + erff(v2 * 0.70710678118654752f));
                v3 = 0.5f * v3 * (1.0f + erff(v3 * 0.70710678118654752f));
            }
            *(float2*)(C + (size_t)r0 * N + c0)       = make_float2(v0, v1);
            *(float2*)(C + (size_t)(r0 + 8) * N + c0) = make_float2(v2, v3);
        }
    }
}

// ---------------- narrow tf32 GEMM: 128x64 tile, 3-stage ring, for x_proj (N=40) ----------------
__global__ void __launch_bounds__(256)
tgemm64_kernel(const float* __restrict__ A, const float* __restrict__ W,
               float* __restrict__ C, int M, int N, int K) {
    __shared__ float Asm[3][128 * TG_STRIDE];
    __shared__ float Wsm[3][64 * TG_STRIDE];

    const int tid  = threadIdx.x;
    const int warp = tid >> 5;
    const int lane = tid & 31;
    const int gid  = lane >> 2;
    const int tig  = lane & 3;
    const int warp_m = warp >> 1;
    const int warp_n = warp & 1;

    const int brow = blockIdx.y << 7;

    const int l_row = tid >> 1;
    const int l_k0  = (tid & 1) * 8;
    const float* Ag = A + (size_t)(brow + l_row) * K + l_k0;

    const int w_row = tid >> 2;
    const int w_k0  = (tid & 3) * 4;
    int wr = w_row < N ? w_row : N - 1;
    const float* Wg = W + (size_t)wr * K + w_k0;

    uint32_t sA[3], sW[3];
#pragma unroll
    for (int s = 0; s < 3; s++) {
        sA[s] = smem_u32(&Asm[s][l_row * TG_STRIDE + l_k0]);
        sW[s] = smem_u32(&Wsm[s][w_row * TG_STRIDE + w_k0]);
    }

    float acc[2][4][4];
#pragma unroll
    for (int i = 0; i < 2; i++)
#pragma unroll
        for (int j = 0; j < 4; j++)
#pragma unroll
            for (int r = 0; r < 4; r++) acc[i][j][r] = 0.f;

    const int nk = K >> 4;
#pragma unroll
    for (int s = 0; s < 2; s++) {
        if (s < nk) {
            const float* Ar = Ag + s * 16;
            cp16(sA[s],      Ar);
            cp16(sA[s] + 16, Ar + 4);
            cp16(sW[s], Wg + s * 16);
        }
        cp_commit();
    }

    int stage = 0;
    for (int kt = 0; kt < nk; kt++) {
        cp_wait<1>();
        __syncthreads();

        int ns = stage + 2; if (ns >= 3) ns -= 3;
        if (kt + 2 < nk) {
            const float* Ar = Ag + (kt + 2) * 16;
            cp16(sA[ns],      Ar);
            cp16(sA[ns] + 16, Ar + 4);
            cp16(sW[ns], Wg + (kt + 2) * 16);
        }
        cp_commit();

        const float* Ab = Asm[stage];
        const float* Wb = Wsm[stage];
#pragma unroll
        for (int ks = 0; ks < 16; ks += 8) {
            uint32_t afr[2][4];
#pragma unroll
            for (int mf = 0; mf < 2; mf++) {
                int r0 = (warp_m * 32 + mf * 16 + gid) * TG_STRIDE + ks + tig;
                afr[mf][0] = fau(Ab[r0]);
                afr[mf][1] = fau(Ab[r0 + 8 * TG_STRIDE]);
                afr[mf][2] = fau(Ab[r0 + 4]);
                afr[mf][3] = fau(Ab[r0 + 8 * TG_STRIDE + 4]);
            }
            uint32_t bfr[4][2];
#pragma unroll
            for (int nf = 0; nf < 4; nf++) {
                int n0 = (warp_n * 32 + nf * 8 + gid) * TG_STRIDE + ks + tig;
                bfr[nf][0] = fau(Wb[n0]);
                bfr[nf][1] = fau(Wb[n0 + 4]);
            }
#pragma unroll
            for (int mf = 0; mf < 2; mf++)
#pragma unroll
                for (int nf = 0; nf < 4; nf++)
                    mma_tf32(acc[mf][nf], afr[mf], bfr[nf]);
        }

        stage++; if (stage == 3) stage = 0;
    }

#pragma unroll
    for (int mf = 0; mf < 2; mf++) {
        int r0 = brow + warp_m * 32 + mf * 16 + gid;
#pragma unroll
        for (int nf = 0; nf < 4; nf++) {
            int c0 = warp_n * 32 + nf * 8 + tig * 2;
            if (c0 < N) {
                *(float2*)(C + (size_t)r0 * N + c0) =
                    make_float2(acc[mf][nf][0], acc[mf][nf][1]);
                *(float2*)(C + (size_t)(r0 + 8) * N + c0) =
                    make_float2(acc[mf][nf][2], acc[mf][nf][3]);
            }
        }
    }
}

// ---------------- depthwise causal conv (k=4) + SiLU ----------------
__global__ void conv_silu_kernel(const float* __restrict__ xz, const float* __restrict__ cw,
                                 const float* __restrict__ cb, float* __restrict__ xc) {
    int bv = blockIdx.x;
    int chunk = blockIdx.y;
    int d = threadIdx.x;
    float w0 = cw[d * 4 + 0], w1 = cw[d * 4 + 1], w2 = cw[d * 4 + 2], w3 = cw[d * 4 + 3];
    float bsv = cb[d];
    int t0 = chunk * 32;
    const float* base = xz + ((size_t)bv * SEQ) * (2 * DI) + d;
    float x0 = (t0 - 3 >= 0) ? base[(size_t)(t0 - 3) * (2 * DI)] : 0.f;
    float x1 = (t0 - 2 >= 0) ? base[(size_t)(t0 - 2) * (2 * DI)] : 0.f;
    float x2 = (t0 - 1 >= 0) ? base[(size_t)(t0 - 1) * (2 * DI)] : 0.f;
#pragma unroll 8
    for (int tt = 0; tt < 32; tt++) {
        int t = t0 + tt;
        float x3 = base[(size_t)t * (2 * DI)];
        float v = w0 * x0 + w1 * x1 + w2 * x2 + w3 * x3 + bsv;
        float s = v / (1.0f + __expf(-v));
        xc[((size_t)bv * SEQ + t) * DI + d] = s;
        x0 = x1; x1 = x2; x2 = x3;
    }
}

// ---------------- dt_proj (K=8) + FAST softplus, 32 rows per block ----------------
__global__ void dt_softplus_kernel(const float* __restrict__ xdbl, const float* __restrict__ dtw,
                                   const float* __restrict__ dtb, float* __restrict__ delta) {
    __shared__ float dts[32][DTR];
    const int r0 = blockIdx.x * 32;
    const int tid = threadIdx.x;
    {
        int r = tid >> 3, c = tid & 7;
        dts[r][c] = xdbl[(size_t)(r0 + r) * 40 + c];
    }
    __syncthreads();
    const int d = tid;
    float w[DTR];
#pragma unroll
    for (int r = 0; r < DTR; r++) w[r] = dtw[d * DTR + r];
    const float b = dtb[d];
#pragma unroll 4
    for (int rr = 0; rr < 32; rr++) {
        float acc = b;
#pragma unroll
        for (int c = 0; c < DTR; c++) acc = fmaf(dts[rr][c], w[c], acc);
        // softplus(x) = max(x,0) + log(1 + exp(-|x|)), branchless & fast
        float sp = fmaxf(acc, 0.f) + __logf(1.0f + __expf(-fabsf(acc)));
        delta[(size_t)(r0 + rr) * DI + d] = sp;
    }
}

// ---------------- selective scan: 4 states/lane, 8 d/warp, depth-4 prefetch ----------------
// warp = 8 d-channels (g = lane>>2), lane i = lane&3 holds states s = i*4..i*4+3
__global__ void __launch_bounds__(128)
scan_kernel(const float* __restrict__ xc, const float* __restrict__ delta,
            const float* __restrict__ xdbl, const float* __restrict__ xz,
            const float* __restrict__ A_log, const float* __restrict__ Dp,
            float* __restrict__ y) {
    const int PF = 4;
    int gw   = (blockIdx.x * 128 + threadIdx.x) >> 5;   // 0..1023
    int lane = threadIdx.x & 31;
    int bv = gw >> 5;          // 32 warps per bv
    int dw = gw & 31;          // 8-d block
    int g  = lane >> 2;        // 0..7
    int i  = lane & 3;         // state group
    int d  = dw * 8 + g;

    float4 al = *(const float4*)(A_log + d * DS + i * 4);
    float a0 = -__expf(al.x), a1 = -__expf(al.y), a2 = -__expf(al.z), a3 = -__expf(al.w);
    float Dval = Dp[d];
    float h0 = 0.f, h1 = 0.f, h2 = 0.f, h3 = 0.f;

    const float* pu  = xc    + (size_t)bv * SEQ * DI + d;
    const float* pdl = delta + (size_t)bv * SEQ * DI + d;
    const float* pB  = xdbl  + (size_t)bv * SEQ * 40 + DTR + i * 4;
    const float* pC  = pB + DS;
    const float* pz  = xz    + (size_t)bv * SEQ * (2 * DI) + DI + d;
    float* py        = y     + (size_t)bv * SEQ * DI + d;

    float uf[PF], dlf[PF], zf[PF];
    float4 Bf[PF], Cf[PF];
#pragma unroll
    for (int k = 0; k < PF; k++) {
        uf[k]  = pu[k * DI];
        dlf[k] = pdl[k * DI];
        Bf[k]  = *(const float4*)(pB + k * 40);
        Cf[k]  = *(const float4*)(pC + k * 40);
        zf[k]  = pz[(size_t)k * (2 * DI)];
    }

    for (int t0 = 0; t0 < SEQ; t0 += PF) {
#pragma unroll
        for (int k = 0; k < PF; k++) {
            float u = uf[k], dl = dlf[k], zv = zf[k];
            float4 B = Bf[k], C = Cf[k];
            int tp = t0 + k + PF;
            if (tp < SEQ) {
                uf[k]  = pu[tp * DI];
                dlf[k] = pdl[tp * DI];
                Bf[k]  = *(const float4*)(pB + tp * 40);
                Cf[k]  = *(const float4*)(pC + tp * 40);
                zf[k]  = pz[(size_t)tp * (2 * DI)];
            }
            float dlu = dl * u;
            h0 = fmaf(__expf(dl * a0), h0, dlu * B.x);
            h1 = fmaf(__expf(dl * a1), h1, dlu * B.y);
            h2 = fmaf(__expf(dl * a2), h2, dlu * B.z);
            h3 = fmaf(__expf(dl * a3), h3, dlu * B.w);
            float p = h0 * C.x;
            p = fmaf(h1, C.y, p);
            p = fmaf(h2, C.z, p);
            p = fmaf(h3, C.w, p);
            p += __shfl_xor_sync(0xffffffffu, p, 1);
            p += __shfl_xor_sync(0xffffffffu, p, 2);
            if (i == 0) {
                float silz = zv / (1.0f + __expf(-zv));
                py[(size_t)(t0 + k) * DI] = (p + u * Dval) * silz;
            }
        }
    }
}

// ---------------- final transpose: h[bv,n,dm] -> out[bv,dm,n] ----------------
__global__ void out_transpose_kernel(const float* __restrict__ hbuf, float* __restrict__ out) {
    __shared__ float tile[32][33];
    int bv = blockIdx.x, nc = blockIdx.y, dc = blockIdx.z;
    int tx = threadIdx.x, ty = threadIdx.y;
    tile[ty][tx] = hbuf[((size_t)bv * SEQ + nc * 32 + ty) * DMOD + dc * 32 + tx];
    __syncthreads();
    out[((size_t)bv * DMOD + dc * 32 + ty) * SEQ + nc * 32 + tx] = tile[tx][ty];
}

// ---------------- launch ----------------
extern "C" void kernel_launch(void* const* d_in, const int* in_sizes, int n_in,
                              void* d_out, int out_size) {
    const float* x         = (const float*)d_in[0];
    const float* W_P_w     = (const float*)d_in[1];
    const float* W_P_b     = (const float*)d_in[2];
    const float* in_proj_w = (const float*)d_in[3];
    const float* conv_w    = (const float*)d_in[4];
    const float* conv_b    = (const float*)d_in[5];
    const float* x_proj_w  = (const float*)d_in[6];
    const float* dt_proj_w = (const float*)d_in[7];
    const float* dt_proj_b = (const float*)d_in[8];
    const float* A_log     = (const float*)d_in[9];
    const float* Dp        = (const float*)d_in[10];
    const float* out_proj_w= (const float*)d_in[11];
    const float* lin1_w    = (const float*)d_in[12];
    const float* lin1_b    = (const float*)d_in[13];
    const float* lin2_w    = (const float*)d_in[14];
    const float* lin2_b    = (const float*)d_in[15];
    float* out = (float*)d_out;

    float *hin, *h, *xz, *xc, *xdbl, *delta, *y, *h2, *ff;
    cudaGetSymbolAddress((void**)&hin,   g_hin);
    cudaGetSymbolAddress((void**)&h,     g_h);
    cudaGetSymbolAddress((void**)&xz,    g_xz);
    cudaGetSymbolAddress((void**)&xc,    g_xc);
    cudaGetSymbolAddress((void**)&xdbl,  g_xdbl);
    cudaGetSymbolAddress((void**)&delta, g_delta);
    cudaGetSymbolAddress((void**)&y,     g_y);
    cudaGetSymbolAddress((void**)&h2,    g_h2);
    cudaGetSymbolAddress((void**)&ff,    g_ff);

    static bool attr_done = false;
    if (!attr_done) {
        cudaFuncSetAttribute(tgemm_kernel<0>, cudaFuncAttributeMaxDynamicSharedMemorySize, TG_SMEM_BYTES);
        cudaFuncSetAttribute(tgemm_kernel<1>, cudaFuncAttributeMaxDynamicSharedMemorySize, TG_SMEM_BYTES);
        attr_done = true;
    }

    const int MT = NROWS / 128;

    patch_transpose_kernel<<<dim3(32, 16), 256>>>(x, hin);
    tgemm_kernel<0><<<dim3(1, MT), 256, TG_SMEM_BYTES>>>(hin, W_P_w, W_P_b, h, NROWS, DMOD, PLEN);

    for (int l = 0; l < 2; l++) {
        const float* ipw = in_proj_w  + (size_t)l * (2 * DI) * DMOD;
        const float* cwp = conv_w     + (size_t)l * DI * 4;
        const float* cbp = conv_b     + (size_t)l * DI;
        const float* xpw = x_proj_w   + (size_t)l * 40 * DI;
        const float* dpw = dt_proj_w  + (size_t)l * DI * DTR;
        const float* dpb = dt_proj_b  + (size_t)l * DI;
        const float* alg = A_log      + (size_t)l * DI * DS;
        const float* dvp = Dp         + (size_t)l * DI;
        const float* opw = out_proj_w + (size_t)l * DMOD * DI;
        const float* l1w = lin1_w     + (size_t)l * DFF * DMOD;
        const float* l1b = lin1_b     + (size_t)l * DFF;
        const float* l2w = lin2_w     + (size_t)l * DMOD * DFF;
        const float* l2b = lin2_b     + (size_t)l * DMOD;

        tgemm_kernel<0><<<dim3(4, MT), 256, TG_SMEM_BYTES>>>(h, ipw, nullptr, xz, NROWS, 2 * DI, DMOD);
        conv_silu_kernel<<<dim3(32, 32), 256>>>(xz, cwp, cbp, xc);
        tgemm64_kernel<<<dim3(1, MT), 256>>>(xc, xpw, xdbl, NROWS, 40, DI);
        dt_softplus_kernel<<<NROWS / 32, 256>>>(xdbl, dpw, dpb, delta);
        scan_kernel<<<256, 128>>>(xc, delta, xdbl, xz, alg, dvp, y);
        tgemm_kernel<0><<<dim3(1, MT), 256, TG_SMEM_BYTES>>>(y, opw, nullptr, h2, NROWS, DMOD, DI);
        tgemm_kernel<1><<<dim3(2, MT), 256, TG_SMEM_BYTES>>>(h2, l1w, l1b, ff, NROWS, DFF, DMOD);
        tgemm_kernel<0><<<dim3(1, MT), 256, TG_SMEM_BYTES>>>(ff, l2w, l2b, h, NROWS, DMOD, DFF);
    }

    out_transpose_kernel<<<dim3(32, 32, 4), dim3(32, 32)>>>(h, out);
}

// round 7
// speedup vs baseline: 2.8283x; 1.0704x over previous
#include <cuda_runtime.h>
#include <cuda_bf16.h>
#include <math.h>
#include <stdint.h>

#define BVn   32
#define SEQ   1024
#define DMOD  128
#define DI    256
#define DS    16
#define DFF   256
#define PLEN  16
#define DTR   8
#define NROWS (BVn*SEQ)   // 32768

typedef __nv_bfloat16 bf16;

// ---------------- scratch (static device globals; no allocation) ----------------
__device__ __align__(256) bf16  g_hinb[NROWS*PLEN];
__device__ __align__(256) bf16  g_hb[NROWS*DMOD];
__device__ __align__(256) float g_h[NROWS*DMOD];
__device__ __align__(256) float g_xz[NROWS*2*DI];
__device__ __align__(256) float g_xc[NROWS*DI];
__device__ __align__(256) float g_xdbl[NROWS*40];
__device__ __align__(256) float g_delta[NROWS*DI];
__device__ __align__(256) bf16  g_yb[NROWS*DI];
__device__ __align__(256) bf16  g_h2b[NROWS*DMOD];
__device__ __align__(256) bf16  g_ffb[NROWS*DFF];
// bf16 weight pool
__device__ __align__(256) bf16  g_wbP[DMOD*PLEN];
__device__ __align__(256) bf16  g_wbin[2*2*DI*DMOD];
__device__ __align__(256) bf16  g_wbout[2*DMOD*DI];
__device__ __align__(256) bf16  g_wbl1[2*DFF*DMOD];
__device__ __align__(256) bf16  g_wbl2[2*DMOD*DFF];

// ---------------- helpers ----------------
__device__ __forceinline__ uint32_t smem_u32(const void* p) {
    return (uint32_t)__cvta_generic_to_shared(p);
}
__device__ __forceinline__ void cp16(uint32_t s, const void* g) {
    asm volatile("cp.async.cg.shared.global [%0], [%1], 16;" :: "r"(s), "l"(g));
}
__device__ __forceinline__ void cp_commit() {
    asm volatile("cp.async.commit_group;");
}
template<int N>
__device__ __forceinline__ void cp_wait() {
    asm volatile("cp.async.wait_group %0;" :: "n"(N));
}
__device__ __forceinline__ void mma_bf16(float* d, const uint32_t* a, const uint32_t* b) {
    asm volatile(
        "mma.sync.aligned.m16n8k16.row.col.f32.bf16.bf16.f32 "
        "{%0,%1,%2,%3}, {%4,%5,%6,%7}, {%8,%9}, {%0,%1,%2,%3};"
        : "+f"(d[0]), "+f"(d[1]), "+f"(d[2]), "+f"(d[3])
        : "r"(a[0]), "r"(a[1]), "r"(a[2]), "r"(a[3]), "r"(b[0]), "r"(b[1]));
}
__device__ __forceinline__ void mma_tf32(float* d, const uint32_t* a, const uint32_t* b) {
    asm volatile(
        "mma.sync.aligned.m16n8k8.row.col.f32.tf32.tf32.f32 "
        "{%0,%1,%2,%3}, {%4,%5,%6,%7}, {%8,%9}, {%0,%1,%2,%3};"
        : "+f"(d[0]), "+f"(d[1]), "+f"(d[2]), "+f"(d[3])
        : "r"(a[0]), "r"(a[1]), "r"(a[2]), "r"(a[3]), "r"(b[0]), "r"(b[1]));
}
__device__ __forceinline__ uint32_t fau(float f) { return __float_as_uint(f); }

// ---------------- f32 -> bf16 convert ----------------
__global__ void f2b_kernel(const float* __restrict__ in, bf16* __restrict__ out, int n) {
    int i = blockIdx.x * blockDim.x + threadIdx.x;
    if (i * 2 + 1 < n) {
        float2 v = *(const float2*)(in + i * 2);
        *(__nv_bfloat162*)(out + i * 2) = __float22bfloat162_rn(v);
    }
}

// ---------------- kernel 1: x (bv,p,n) -> hin_b (bv*n, p) bf16 ----------------
__global__ void patch_transpose_kernel(const float* __restrict__ x, bf16* __restrict__ hin) {
    __shared__ float tile[PLEN][64 + 1];
    int bv = blockIdx.x;
    int nc = blockIdx.y;
    int tid = threadIdx.x;
    const float* xb = x + (size_t)bv * PLEN * SEQ;
#pragma unroll
    for (int r = 0; r < 4; r++) {
        int idx = r * 256 + tid;
        int p = idx >> 6, nl = idx & 63;
        tile[p][nl] = xb[p * SEQ + nc * 64 + nl];
    }
    __syncthreads();
#pragma unroll
    for (int r = 0; r < 4; r++) {
        int nl = r * 16 + (tid >> 4);
        int p = tid & 15;
        hin[((size_t)bv * SEQ + nc * 64 + nl) * PLEN + p] = __float2bfloat16(tile[p][nl]);
    }
}

// ---------------- bf16 tensor GEMM: 128x128 tile, BK=16, 3-stage cp.async ring ----------------
// C[M,N] = A[M,K] @ W[N,K]^T (+bias, +GELU). M%128==0, N%128==0, K%16==0.
// OUTM bit0: write fp32 C; bit1: write bf16 Cb.
// smem row stride = 12 words (24 bf16 = 48B): conflict-free fragment LDS.
#define BG_RS 12
#define BG_ST (128 * BG_RS)
template<int ACT, int OUTM>
__global__ void __launch_bounds__(256)
bgemm_kernel(const bf16* __restrict__ A, const bf16* __restrict__ W,
             const float* __restrict__ bias, float* __restrict__ C,
             bf16* __restrict__ Cb, int M, int N, int K) {
    __shared__ uint32_t As[3][BG_ST];
    __shared__ uint32_t Ws[3][BG_ST];

    const int tid  = threadIdx.x;
    const int warp = tid >> 5;
    const int lane = tid & 31;
    const int gid  = lane >> 2;
    const int tig  = lane & 3;
    const int warp_m = warp >> 2;    // 0..1
    const int warp_n = warp & 3;     // 0..3

    const int brow = blockIdx.y << 7;
    const int bcol = blockIdx.x << 7;

    // loader mapping: thread t -> row = t>>1, half = t&1 (k 0-7 or 8-15)
    const int l_row  = tid >> 1;
    const int l_half = tid & 1;
    const bf16* Ag = A + (size_t)(brow + l_row) * K + l_half * 8;
    const bf16* Wg = W + (size_t)(bcol + l_row) * K + l_half * 8;

    uint32_t sA[3], sW[3];
#pragma unroll
    for (int s = 0; s < 3; s++) {
        sA[s] = smem_u32(&As[s][l_row * BG_RS + l_half * 4]);
        sW[s] = smem_u32(&Ws[s][l_row * BG_RS + l_half * 4]);
    }

    float acc[4][4][4];
#pragma unroll
    for (int i = 0; i < 4; i++)
#pragma unroll
        for (int j = 0; j < 4; j++)
#pragma unroll
            for (int r = 0; r < 4; r++) acc[i][j][r] = 0.f;

    const int nk = K >> 4;

#pragma unroll
    for (int s = 0; s < 2; s++) {
        if (s < nk) {
            cp16(sA[s], Ag + s * 16);
            cp16(sW[s], Wg + s * 16);
        }
        cp_commit();
    }

    int stage = 0;
    for (int kt = 0; kt < nk; kt++) {
        cp_wait<1>();
        __syncthreads();

        int ns = stage + 2; if (ns >= 3) ns -= 3;
        if (kt + 2 < nk) {
            cp16(sA[ns], Ag + (kt + 2) * 16);
            cp16(sW[ns], Wg + (kt + 2) * 16);
        }
        cp_commit();

        const uint32_t* Ab = As[stage];
        const uint32_t* Wb = Ws[stage];

        uint32_t afr[4][4];
#pragma unroll
        for (int mf = 0; mf < 4; mf++) {
            int base = (warp_m * 64 + mf * 16 + gid) * BG_RS + tig;
            afr[mf][0] = Ab[base];
            afr[mf][1] = Ab[base + 8 * BG_RS];
            afr[mf][2] = Ab[base + 4];
            afr[mf][3] = Ab[base + 8 * BG_RS + 4];
        }
        uint32_t bfr[4][2];
#pragma unroll
        for (int nf = 0; nf < 4; nf++) {
            int base = (warp_n * 32 + nf * 8 + gid) * BG_RS + tig;
            bfr[nf][0] = Wb[base];
            bfr[nf][1] = Wb[base + 4];
        }
#pragma unroll
        for (int mf = 0; mf < 4; mf++)
#pragma unroll
            for (int nf = 0; nf < 4; nf++)
                mma_bf16(acc[mf][nf], afr[mf], bfr[nf]);

        stage++; if (stage == 3) stage = 0;
    }

#pragma unroll
    for (int mf = 0; mf < 4; mf++) {
        int r0 = brow + warp_m * 64 + mf * 16 + gid;
#pragma unroll
        for (int nf = 0; nf < 4; nf++) {
            int c0 = bcol + warp_n * 32 + nf * 8 + tig * 2;
            float b0 = bias ? bias[c0] : 0.f;
            float b1 = bias ? bias[c0 + 1] : 0.f;
            float v0 = acc[mf][nf][0] + b0;
            float v1 = acc[mf][nf][1] + b1;
            float v2 = acc[mf][nf][2] + b0;
            float v3 = acc[mf][nf][3] + b1;
            if (ACT == 1) {
                v0 = 0.5f * v0 * (1.0f + erff(v0 * 0.70710678118654752f));
                v1 = 0.5f * v1 * (1.0f + erff(v1 * 0.70710678118654752f));
                v2 = 0.5f * v2 * (1.0f + erff(v2 * 0.70710678118654752f));
                v3 = 0.5f * v3 * (1.0f + erff(v3 * 0.70710678118654752f));
            }
            if (OUTM & 1) {
                *(float2*)(C + (size_t)r0 * N + c0)       = make_float2(v0, v1);
                *(float2*)(C + (size_t)(r0 + 8) * N + c0) = make_float2(v2, v3);
            }
            if (OUTM & 2) {
                *(__nv_bfloat162*)(Cb + (size_t)r0 * N + c0) =
                    __float22bfloat162_rn(make_float2(v0, v1));
                *(__nv_bfloat162*)(Cb + (size_t)(r0 + 8) * N + c0) =
                    __float22bfloat162_rn(make_float2(v2, v3));
            }
        }
    }
}

// ---------------- narrow tf32 GEMM: 128x64 tile, 3-stage ring, for x_proj (N=40) ----------------
#define TG_STRIDE 20
__global__ void __launch_bounds__(256)
tgemm64_kernel(const float* __restrict__ A, const float* __restrict__ W,
               float* __restrict__ C, int M, int N, int K) {
    __shared__ float Asm[3][128 * TG_STRIDE];
    __shared__ float Wsm[3][64 * TG_STRIDE];

    const int tid  = threadIdx.x;
    const int warp = tid >> 5;
    const int lane = tid & 31;
    const int gid  = lane >> 2;
    const int tig  = lane & 3;
    const int warp_m = warp >> 1;
    const int warp_n = warp & 1;

    const int brow = blockIdx.y << 7;

    const int l_row = tid >> 1;
    const int l_k0  = (tid & 1) * 8;
    const float* Ag = A + (size_t)(brow + l_row) * K + l_k0;

    const int w_row = tid >> 2;
    const int w_k0  = (tid & 3) * 4;
    int wr = w_row < N ? w_row : N - 1;
    const float* Wg = W + (size_t)wr * K + w_k0;

    uint32_t sA[3], sW[3];
#pragma unroll
    for (int s = 0; s < 3; s++) {
        sA[s] = smem_u32(&Asm[s][l_row * TG_STRIDE + l_k0]);
        sW[s] = smem_u32(&Wsm[s][w_row * TG_STRIDE + w_k0]);
    }

    float acc[2][4][4];
#pragma unroll
    for (int i = 0; i < 2; i++)
#pragma unroll
        for (int j = 0; j < 4; j++)
#pragma unroll
            for (int r = 0; r < 4; r++) acc[i][j][r] = 0.f;

    const int nk = K >> 4;
#pragma unroll
    for (int s = 0; s < 2; s++) {
        if (s < nk) {
            const float* Ar = Ag + s * 16;
            cp16(sA[s],      Ar);
            cp16(sA[s] + 16, Ar + 4);
            cp16(sW[s], Wg + s * 16);
        }
        cp_commit();
    }

    int stage = 0;
    for (int kt = 0; kt < nk; kt++) {
        cp_wait<1>();
        __syncthreads();

        int ns = stage + 2; if (ns >= 3) ns -= 3;
        if (kt + 2 < nk) {
            const float* Ar = Ag + (kt + 2) * 16;
            cp16(sA[ns],      Ar);
            cp16(sA[ns] + 16, Ar + 4);
            cp16(sW[ns], Wg + (kt + 2) * 16);
        }
        cp_commit();

        const float* Ab = Asm[stage];
        const float* Wb = Wsm[stage];
#pragma unroll
        for (int ks = 0; ks < 16; ks += 8) {
            uint32_t afr[2][4];
#pragma unroll
            for (int mf = 0; mf < 2; mf++) {
                int r0 = (warp_m * 32 + mf * 16 + gid) * TG_STRIDE + ks + tig;
                afr[mf][0] = fau(Ab[r0]);
                afr[mf][1] = fau(Ab[r0 + 8 * TG_STRIDE]);
                afr[mf][2] = fau(Ab[r0 + 4]);
                afr[mf][3] = fau(Ab[r0 + 8 * TG_STRIDE + 4]);
            }
            uint32_t bfr[4][2];
#pragma unroll
            for (int nf = 0; nf < 4; nf++) {
                int n0 = (warp_n * 32 + nf * 8 + gid) * TG_STRIDE + ks + tig;
                bfr[nf][0] = fau(Wb[n0]);
                bfr[nf][1] = fau(Wb[n0 + 4]);
            }
#pragma unroll
            for (int mf = 0; mf < 2; mf++)
#pragma unroll
                for (int nf = 0; nf < 4; nf++)
                    mma_tf32(acc[mf][nf], afr[mf], bfr[nf]);
        }

        stage++; if (stage == 3) stage = 0;
    }

#pragma unroll
    for (int mf = 0; mf < 2; mf++) {
        int r0 = brow + warp_m * 32 + mf * 16 + gid;
#pragma unroll
        for (int nf = 0; nf < 4; nf++) {
            int c0 = warp_n * 32 + nf * 8 + tig * 2;
            if (c0 < N) {
                *(float2*)(C + (size_t)r0 * N + c0) =
                    make_float2(acc[mf][nf][0], acc[mf][nf][1]);
                *(float2*)(C + (size_t)(r0 + 8) * N + c0) =
                    make_float2(acc[mf][nf][2], acc[mf][nf][3]);
            }
        }
    }
}

// ---------------- depthwise causal conv (k=4) + SiLU ----------------
__global__ void conv_silu_kernel(const float* __restrict__ xz, const float* __restrict__ cw,
                                 const float* __restrict__ cb, float* __restrict__ xc) {
    int bv = blockIdx.x;
    int chunk = blockIdx.y;
    int d = threadIdx.x;
    float w0 = cw[d * 4 + 0], w1 = cw[d * 4 + 1], w2 = cw[d * 4 + 2], w3 = cw[d * 4 + 3];
    float bsv = cb[d];
    int t0 = chunk * 32;
    const float* base = xz + ((size_t)bv * SEQ) * (2 * DI) + d;
    float x0 = (t0 - 3 >= 0) ? base[(size_t)(t0 - 3) * (2 * DI)] : 0.f;
    float x1 = (t0 - 2 >= 0) ? base[(size_t)(t0 - 2) * (2 * DI)] : 0.f;
    float x2 = (t0 - 1 >= 0) ? base[(size_t)(t0 - 1) * (2 * DI)] : 0.f;
#pragma unroll 8
    for (int tt = 0; tt < 32; tt++) {
        int t = t0 + tt;
        float x3 = base[(size_t)t * (2 * DI)];
        float v = w0 * x0 + w1 * x1 + w2 * x2 + w3 * x3 + bsv;
        float s = v / (1.0f + __expf(-v));
        xc[((size_t)bv * SEQ + t) * DI + d] = s;
        x0 = x1; x1 = x2; x2 = x3;
    }
}

// ---------------- dt_proj (K=8) + FAST softplus, 32 rows per block ----------------
__global__ void dt_softplus_kernel(const float* __restrict__ xdbl, const float* __restrict__ dtw,
                                   const float* __restrict__ dtb, float* __restrict__ delta) {
    __shared__ float dts[32][DTR];
    const int r0 = blockIdx.x * 32;
    const int tid = threadIdx.x;
    {
        int r = tid >> 3, c = tid & 7;
        dts[r][c] = xdbl[(size_t)(r0 + r) * 40 + c];
    }
    __syncthreads();
    const int d = tid;
    float w[DTR];
#pragma unroll
    for (int r = 0; r < DTR; r++) w[r] = dtw[d * DTR + r];
    const float b = dtb[d];
#pragma unroll 4
    for (int rr = 0; rr < 32; rr++) {
        float acc = b;
#pragma unroll
        for (int c = 0; c < DTR; c++) acc = fmaf(dts[rr][c], w[c], acc);
        float sp = fmaxf(acc, 0.f) + __logf(1.0f + __expf(-fabsf(acc)));
        delta[(size_t)(r0 + rr) * DI + d] = sp;
    }
}

// ---------------- selective scan: 4 states/lane, 8 d/warp, depth-4 prefetch; y -> bf16 ----------------
__global__ void __launch_bounds__(128)
scan_kernel(const float* __restrict__ xc, const float* __restrict__ delta,
            const float* __restrict__ xdbl, const float* __restrict__ xz,
            const float* __restrict__ A_log, const float* __restrict__ Dp,
            bf16* __restrict__ y) {
    const int PF = 4;
    int gw   = (blockIdx.x * 128 + threadIdx.x) >> 5;
    int lane = threadIdx.x & 31;
    int bv = gw >> 5;
    int dw = gw & 31;
    int g  = lane >> 2;
    int i  = lane & 3;
    int d  = dw * 8 + g;

    float4 al = *(const float4*)(A_log + d * DS + i * 4);
    float a0 = -__expf(al.x), a1 = -__expf(al.y), a2 = -__expf(al.z), a3 = -__expf(al.w);
    float Dval = Dp[d];
    float h0 = 0.f, h1 = 0.f, h2 = 0.f, h3 = 0.f;

    const float* pu  = xc    + (size_t)bv * SEQ * DI + d;
    const float* pdl = delta + (size_t)bv * SEQ * DI + d;
    const float* pB  = xdbl  + (size_t)bv * SEQ * 40 + DTR + i * 4;
    const float* pC  = pB + DS;
    const float* pz  = xz    + (size_t)bv * SEQ * (2 * DI) + DI + d;
    bf16* py         = y     + (size_t)bv * SEQ * DI + d;

    float uf[PF], dlf[PF], zf[PF];
    float4 Bf[PF], Cf[PF];
#pragma unroll
    for (int k = 0; k < PF; k++) {
        uf[k]  = pu[k * DI];
        dlf[k] = pdl[k * DI];
        Bf[k]  = *(const float4*)(pB + k * 40);
        Cf[k]  = *(const float4*)(pC + k * 40);
        zf[k]  = pz[(size_t)k * (2 * DI)];
    }

    for (int t0 = 0; t0 < SEQ; t0 += PF) {
#pragma unroll
        for (int k = 0; k < PF; k++) {
            float u = uf[k], dl = dlf[k], zv = zf[k];
            float4 B = Bf[k], C = Cf[k];
            int tp = t0 + k + PF;
            if (tp < SEQ) {
                uf[k]  = pu[tp * DI];
                dlf[k] = pdl[tp * DI];
                Bf[k]  = *(const float4*)(pB + tp * 40);
                Cf[k]  = *(const float4*)(pC + tp * 40);
                zf[k]  = pz[(size_t)tp * (2 * DI)];
            }
            float dlu = dl * u;
            h0 = fmaf(__expf(dl * a0), h0, dlu * B.x);
            h1 = fmaf(__expf(dl * a1), h1, dlu * B.y);
            h2 = fmaf(__expf(dl * a2), h2, dlu * B.z);
            h3 = fmaf(__expf(dl * a3), h3, dlu * B.w);
            float p = h0 * C.x;
            p = fmaf(h1, C.y, p);
            p = fmaf(h2, C.z, p);
            p = fmaf(h3, C.w, p);
            p += __shfl_xor_sync(0xffffffffu, p, 1);
            p += __shfl_xor_sync(0xffffffffu, p, 2);
            if (i == 0) {
                float silz = zv / (1.0f + __expf(-zv));
                py[(size_t)(t0 + k) * DI] = __float2bfloat16((p + u * Dval) * silz);
            }
        }
    }
}

// ---------------- final transpose: h[bv,n,dm] -> out[bv,dm,n] ----------------
__global__ void out_transpose_kernel(const float* __restrict__ hbuf, float* __restrict__ out) {
    __shared__ float tile[32][33];
    int bv = blockIdx.x, nc = blockIdx.y, dc = blockIdx.z;
    int tx = threadIdx.x, ty = threadIdx.y;
    tile[ty][tx] = hbuf[((size_t)bv * SEQ + nc * 32 + ty) * DMOD + dc * 32 + tx];
    __syncthreads();
    out[((size_t)bv * DMOD + dc * 32 + ty) * SEQ + nc * 32 + tx] = tile[tx][ty];
}

// ---------------- launch ----------------
extern "C" void kernel_launch(void* const* d_in, const int* in_sizes, int n_in,
                              void* d_out, int out_size) {
    const float* x         = (const float*)d_in[0];
    const float* W_P_w     = (const float*)d_in[1];
    const float* W_P_b     = (const float*)d_in[2];
    const float* in_proj_w = (const float*)d_in[3];
    const float* conv_w    = (const float*)d_in[4];
    const float* conv_b    = (const float*)d_in[5];
    const float* x_proj_w  = (const float*)d_in[6];
    const float* dt_proj_w = (const float*)d_in[7];
    const float* dt_proj_b = (const float*)d_in[8];
    const float* A_log     = (const float*)d_in[9];
    const float* Dp        = (const float*)d_in[10];
    const float* out_proj_w= (const float*)d_in[11];
    const float* lin1_w    = (const float*)d_in[12];
    const float* lin1_b    = (const float*)d_in[13];
    const float* lin2_w    = (const float*)d_in[14];
    const float* lin2_b    = (const float*)d_in[15];
    float* out = (float*)d_out;

    bf16 *hinb, *hb, *yb, *h2b, *ffb, *wbP, *wbin, *wbout, *wbl1, *wbl2;
    float *h, *xz, *xc, *xdbl, *delta;
    cudaGetSymbolAddress((void**)&hinb,  g_hinb);
    cudaGetSymbolAddress((void**)&hb,    g_hb);
    cudaGetSymbolAddress((void**)&h,     g_h);
    cudaGetSymbolAddress((void**)&xz,    g_xz);
    cudaGetSymbolAddress((void**)&xc,    g_xc);
    cudaGetSymbolAddress((void**)&xdbl,  g_xdbl);
    cudaGetSymbolAddress((void**)&delta, g_delta);
    cudaGetSymbolAddress((void**)&yb,    g_yb);
    cudaGetSymbolAddress((void**)&h2b,   g_h2b);
    cudaGetSymbolAddress((void**)&ffb,   g_ffb);
    cudaGetSymbolAddress((void**)&wbP,   g_wbP);
    cudaGetSymbolAddress((void**)&wbin,  g_wbin);
    cudaGetSymbolAddress((void**)&wbout, g_wbout);
    cudaGetSymbolAddress((void**)&wbl1,  g_wbl1);
    cudaGetSymbolAddress((void**)&wbl2,  g_wbl2);

    // weight conversions (deterministic each call)
    {
        int n;
        n = DMOD * PLEN;        f2b_kernel<<<(n/2 + 255)/256, 256>>>(W_P_w,      wbP,   n);
        n = 2 * 2*DI * DMOD;    f2b_kernel<<<(n/2 + 255)/256, 256>>>(in_proj_w,  wbin,  n);
        n = 2 * DMOD * DI;      f2b_kernel<<<(n/2 + 255)/256, 256>>>(out_proj_w, wbout, n);
        n = 2 * DFF * DMOD;     f2b_kernel<<<(n/2 + 255)/256, 256>>>(lin1_w,     wbl1,  n);
        n = 2 * DMOD * DFF;     f2b_kernel<<<(n/2 + 255)/256, 256>>>(lin2_w,     wbl2,  n);
    }

    const int MT = NROWS / 128;

    patch_transpose_kernel<<<dim3(32, 16), 256>>>(x, hinb);
    // embed: bf16-only output (h consumed only by in_proj)
    bgemm_kernel<0, 2><<<dim3(1, MT), 256>>>(hinb, wbP, W_P_b, nullptr, hb, NROWS, DMOD, PLEN);

    for (int l = 0; l < 2; l++) {
        const bf16*  ipw = wbin  + (size_t)l * (2 * DI) * DMOD;
        const float* cwp = conv_w + (size_t)l * DI * 4;
        const float* cbp = conv_b + (size_t)l * DI;
        const float* xpw = x_proj_w + (size_t)l * 40 * DI;
        const float* dpw = dt_proj_w + (size_t)l * DI * DTR;
        const float* dpb = dt_proj_b + (size_t)l * DI;
        const float* alg = A_log + (size_t)l * DI * DS;
        const float* dvp = Dp + (size_t)l * DI;
        const bf16*  opw = wbout + (size_t)l * DMOD * DI;
        const bf16*  l1w = wbl1 + (size_t)l * DFF * DMOD;
        const float* l1b = lin1_b + (size_t)l * DFF;
        const bf16*  l2w = wbl2 + (size_t)l * DMOD * DFF;
        const float* l2b = lin2_b + (size_t)l * DMOD;

        bgemm_kernel<0, 1><<<dim3(4, MT), 256>>>(hb, ipw, nullptr, xz, nullptr, NROWS, 2 * DI, DMOD);
        conv_silu_kernel<<<dim3(32, 32), 256>>>(xz, cwp, cbp, xc);
        tgemm64_kernel<<<dim3(1, MT), 256>>>(xc, xpw, xdbl, NROWS, 40, DI);
        dt_softplus_kernel<<<NROWS / 32, 256>>>(xdbl, dpw, dpb, delta);
        scan_kernel<<<256, 128>>>(xc, delta, xdbl, xz, alg, dvp, yb);
        bgemm_kernel<0, 2><<<dim3(1, MT), 256>>>(yb, opw, nullptr, nullptr, h2b, NROWS, DMOD, DI);
        bgemm_kernel<1, 2><<<dim3(2, MT), 256>>>(h2b, l1w, l1b, nullptr, ffb, NROWS, DFF, DMOD);
        bgemm_kernel<0, 3><<<dim3(1, MT), 256>>>(ffb, l2w, l2b, h, hb, NROWS, DMOD, DFF);
    }

    out_transpose_kernel<<<dim3(32, 32, 4), dim3(32, 32)>>>(h, out);
}

// round 8
// speedup vs baseline: 3.9885x; 1.4102x over previous
#include <cuda_runtime.h>
#include <cuda_bf16.h>
#include <math.h>
#include <stdint.h>

#define BVn   32
#define SEQ   1024
#define DMOD  128
#define DI    256
#define DS    16
#define DFF   256
#define PLEN  16
#define DTR   8
#define NROWS (BVn*SEQ)   // 32768

typedef __nv_bfloat16 bf16;

// ---------------- scratch ----------------
__device__ __align__(256) bf16  g_hinb[NROWS*PLEN];
__device__ __align__(256) bf16  g_hb[NROWS*DMOD];
__device__ __align__(256) float g_h[NROWS*DMOD];
__device__ __align__(256) float g_xin[NROWS*DI];     // in_proj x half (fp32, dense)
__device__ __align__(256) bf16  g_zb[NROWS*DI];      // silu(z) bf16
__device__ __align__(256) float g_xc[NROWS*DI];
__device__ __align__(256) bf16  g_xcb[NROWS*DI];
__device__ __align__(256) float g_xdbl[NROWS*40];
__device__ __align__(256) float g_delta[NROWS*DI];
__device__ __align__(256) bf16  g_yb[NROWS*DI];
__device__ __align__(256) bf16  g_h2b[NROWS*DMOD];
__device__ __align__(256) bf16  g_ffb[NROWS*DFF];
// bf16 weights
__device__ __align__(256) bf16  g_wbP[DMOD*PLEN];
__device__ __align__(256) bf16  g_wbin[2*2*DI*DMOD];
__device__ __align__(256) bf16  g_wbout[2*DMOD*DI];
__device__ __align__(256) bf16  g_wbl1[2*DFF*DMOD];
__device__ __align__(256) bf16  g_wbl2[2*DMOD*DFF];
__device__ __align__(256) bf16  g_wbxp[2*40*DI];

// ---------------- helpers ----------------
__device__ __forceinline__ uint32_t smem_u32(const void* p) {
    return (uint32_t)__cvta_generic_to_shared(p);
}
__device__ __forceinline__ void cp16(uint32_t s, const void* g) {
    asm volatile("cp.async.cg.shared.global [%0], [%1], 16;" :: "r"(s), "l"(g));
}
__device__ __forceinline__ void cp_commit() {
    asm volatile("cp.async.commit_group;");
}
template<int N>
__device__ __forceinline__ void cp_wait() {
    asm volatile("cp.async.wait_group %0;" :: "n"(N));
}
__device__ __forceinline__ void mma_bf16(float* d, const uint32_t* a, const uint32_t* b) {
    asm volatile(
        "mma.sync.aligned.m16n8k16.row.col.f32.bf16.bf16.f32 "
        "{%0,%1,%2,%3}, {%4,%5,%6,%7}, {%8,%9}, {%0,%1,%2,%3};"
        : "+f"(d[0]), "+f"(d[1]), "+f"(d[2]), "+f"(d[3])
        : "r"(a[0]), "r"(a[1]), "r"(a[2]), "r"(a[3]), "r"(b[0]), "r"(b[1]));
}

// ---------------- batched f32 -> bf16 weight convert ----------------
__global__ void f2b_all_kernel(const float* s0, bf16* d0, int n0,
                               const float* s1, bf16* d1, int n1,
                               const float* s2, bf16* d2, int n2,
                               const float* s3, bf16* d3, int n3,
                               const float* s4, bf16* d4, int n4,
                               const float* s5, bf16* d5, int n5) {
    int i = (blockIdx.x * blockDim.x + threadIdx.x) * 2;
    const float* s; bf16* d; int off = i;
    if      (off < n0) { s = s0; d = d0; }
    else if ((off -= n0) < n1) { s = s1; d = d1; }
    else if ((off -= n1) < n2) { s = s2; d = d2; }
    else if ((off -= n2) < n3) { s = s3; d = d3; }
    else if ((off -= n3) < n4) { s = s4; d = d4; }
    else if ((off -= n4) < n5) { s = s5; d = d5; }
    else return;
    float2 v = *(const float2*)(s + off);
    *(__nv_bfloat162*)(d + off) = __float22bfloat162_rn(v);
}

// ---------------- x (bv,p,n) -> hin_b (bv*n, p) bf16 ----------------
__global__ void patch_transpose_kernel(const float* __restrict__ x, bf16* __restrict__ hin) {
    __shared__ float tile[PLEN][64 + 1];
    int bv = blockIdx.x;
    int nc = blockIdx.y;
    int tid = threadIdx.x;
    const float* xb = x + (size_t)bv * PLEN * SEQ;
#pragma unroll
    for (int r = 0; r < 4; r++) {
        int idx = r * 256 + tid;
        int p = idx >> 6, nl = idx & 63;
        tile[p][nl] = xb[p * SEQ + nc * 64 + nl];
    }
    __syncthreads();
#pragma unroll
    for (int r = 0; r < 4; r++) {
        int nl = r * 16 + (tid >> 4);
        int p = tid & 15;
        hin[((size_t)bv * SEQ + nc * 64 + nl) * PLEN + p] = __float2bfloat16(tile[p][nl]);
    }
}

// ---------------- bf16 GEMM 128x128, BK=16, 3-stage cp.async ----------------
// OUTM: 1 = fp32 C; 2 = bf16 Cb; 3 = both; 4 = in_proj split (xin fp32 | silu(z) bf16)
#define BG_RS 12
#define BG_ST (128 * BG_RS)
template<int ACT, int OUTM>
__global__ void __launch_bounds__(256)
bgemm_kernel(const bf16* __restrict__ A, const bf16* __restrict__ W,
             const float* __restrict__ bias, float* __restrict__ C,
             bf16* __restrict__ Cb, int M, int N, int K) {
    __shared__ uint32_t As[3][BG_ST];
    __shared__ uint32_t Ws[3][BG_ST];

    const int tid  = threadIdx.x;
    const int warp = tid >> 5;
    const int lane = tid & 31;
    const int gid  = lane >> 2;
    const int tig  = lane & 3;
    const int warp_m = warp >> 2;
    const int warp_n = warp & 3;

    const int brow = blockIdx.y << 7;
    const int bcol = blockIdx.x << 7;

    const int l_row  = tid >> 1;
    const int l_half = tid & 1;
    const bf16* Ag = A + (size_t)(brow + l_row) * K + l_half * 8;
    const bf16* Wg = W + (size_t)(bcol + l_row) * K + l_half * 8;

    uint32_t sA[3], sW[3];
#pragma unroll
    for (int s = 0; s < 3; s++) {
        sA[s] = smem_u32(&As[s][l_row * BG_RS + l_half * 4]);
        sW[s] = smem_u32(&Ws[s][l_row * BG_RS + l_half * 4]);
    }

    float acc[4][4][4];
#pragma unroll
    for (int i = 0; i < 4; i++)
#pragma unroll
        for (int j = 0; j < 4; j++)
#pragma unroll
            for (int r = 0; r < 4; r++) acc[i][j][r] = 0.f;

    const int nk = K >> 4;

#pragma unroll
    for (int s = 0; s < 2; s++) {
        if (s < nk) {
            cp16(sA[s], Ag + s * 16);
            cp16(sW[s], Wg + s * 16);
        }
        cp_commit();
    }

    int stage = 0;
    for (int kt = 0; kt < nk; kt++) {
        cp_wait<1>();
        __syncthreads();

        int ns = stage + 2; if (ns >= 3) ns -= 3;
        if (kt + 2 < nk) {
            cp16(sA[ns], Ag + (kt + 2) * 16);
            cp16(sW[ns], Wg + (kt + 2) * 16);
        }
        cp_commit();

        const uint32_t* Ab = As[stage];
        const uint32_t* Wb = Ws[stage];

        uint32_t afr[4][4];
#pragma unroll
        for (int mf = 0; mf < 4; mf++) {
            int base = (warp_m * 64 + mf * 16 + gid) * BG_RS + tig;
            afr[mf][0] = Ab[base];
            afr[mf][1] = Ab[base + 8 * BG_RS];
            afr[mf][2] = Ab[base + 4];
            afr[mf][3] = Ab[base + 8 * BG_RS + 4];
        }
        uint32_t bfr[4][2];
#pragma unroll
        for (int nf = 0; nf < 4; nf++) {
            int base = (warp_n * 32 + nf * 8 + gid) * BG_RS + tig;
            bfr[nf][0] = Wb[base];
            bfr[nf][1] = Wb[base + 4];
        }
#pragma unroll
        for (int mf = 0; mf < 4; mf++)
#pragma unroll
            for (int nf = 0; nf < 4; nf++)
                mma_bf16(acc[mf][nf], afr[mf], bfr[nf]);

        stage++; if (stage == 3) stage = 0;
    }

#pragma unroll
    for (int mf = 0; mf < 4; mf++) {
        int r0 = brow + warp_m * 64 + mf * 16 + gid;
#pragma unroll
        for (int nf = 0; nf < 4; nf++) {
            int c0 = bcol + warp_n * 32 + nf * 8 + tig * 2;
            float b0 = bias ? bias[c0] : 0.f;
            float b1 = bias ? bias[c0 + 1] : 0.f;
            float v0 = acc[mf][nf][0] + b0;
            float v1 = acc[mf][nf][1] + b1;
            float v2 = acc[mf][nf][2] + b0;
            float v3 = acc[mf][nf][3] + b1;
            if (ACT == 1) {
                v0 = 0.5f * v0 * (1.0f + erff(v0 * 0.70710678118654752f));
                v1 = 0.5f * v1 * (1.0f + erff(v1 * 0.70710678118654752f));
                v2 = 0.5f * v2 * (1.0f + erff(v2 * 0.70710678118654752f));
                v3 = 0.5f * v3 * (1.0f + erff(v3 * 0.70710678118654752f));
            }
            if (OUTM == 4) {
                // in_proj split: cols [0,256) -> fp32 xin (stride 256);
                //                cols [256,512) -> silu -> bf16 zb (stride 256)
                if (c0 < DI) {
                    *(float2*)(C + (size_t)r0 * DI + c0)       = make_float2(v0, v1);
                    *(float2*)(C + (size_t)(r0 + 8) * DI + c0) = make_float2(v2, v3);
                } else {
                    int zc = c0 - DI;
                    float s0 = v0 / (1.0f + __expf(-v0));
                    float s1 = v1 / (1.0f + __expf(-v1));
                    float s2 = v2 / (1.0f + __expf(-v2));
                    float s3 = v3 / (1.0f + __expf(-v3));
                    *(__nv_bfloat162*)(Cb + (size_t)r0 * DI + zc) =
                        __float22bfloat162_rn(make_float2(s0, s1));
                    *(__nv_bfloat162*)(Cb + (size_t)(r0 + 8) * DI + zc) =
                        __float22bfloat162_rn(make_float2(s2, s3));
                }
            } else {
                if (OUTM & 1) {
                    *(float2*)(C + (size_t)r0 * N + c0)       = make_float2(v0, v1);
                    *(float2*)(C + (size_t)(r0 + 8) * N + c0) = make_float2(v2, v3);
                }
                if (OUTM & 2) {
                    *(__nv_bfloat162*)(Cb + (size_t)r0 * N + c0) =
                        __float22bfloat162_rn(make_float2(v0, v1));
                    *(__nv_bfloat162*)(Cb + (size_t)(r0 + 8) * N + c0) =
                        __float22bfloat162_rn(make_float2(v2, v3));
                }
            }
        }
    }
}

// ---------------- bf16 GEMM 128x64 (x_proj, N=40) ----------------
__global__ void __launch_bounds__(256)
bgemm64_kernel(const bf16* __restrict__ A, const bf16* __restrict__ W,
               float* __restrict__ C, int M, int N, int K) {
    __shared__ uint32_t As[3][BG_ST];
    __shared__ uint32_t Ws[3][64 * BG_RS];

    const int tid  = threadIdx.x;
    const int warp = tid >> 5;
    const int lane = tid & 31;
    const int gid  = lane >> 2;
    const int tig  = lane & 3;
    const int warp_m = warp >> 1;   // 0..3 (32 rows)
    const int warp_n = warp & 1;    // 0..1 (32 cols)

    const int brow = blockIdx.y << 7;

    const int l_row  = tid >> 1;
    const int l_half = tid & 1;
    const bf16* Ag = A + (size_t)(brow + l_row) * K + l_half * 8;

    // W loader: threads 0..127 cover 64 rows x 2 halves
    const int w_row  = tid >> 1;          // 0..63 for tid<128
    int wr = w_row < N ? w_row : N - 1;
    const bf16* Wg = W + (size_t)wr * K + l_half * 8;
    const bool wload = tid < 128;

    uint32_t sA[3], sW[3];
#pragma unroll
    for (int s = 0; s < 3; s++) {
        sA[s] = smem_u32(&As[s][l_row * BG_RS + l_half * 4]);
        sW[s] = smem_u32(&Ws[s][w_row * BG_RS + l_half * 4]);
    }

    float acc[2][4][4];
#pragma unroll
    for (int i = 0; i < 2; i++)
#pragma unroll
        for (int j = 0; j < 4; j++)
#pragma unroll
            for (int r = 0; r < 4; r++) acc[i][j][r] = 0.f;

    const int nk = K >> 4;
#pragma unroll
    for (int s = 0; s < 2; s++) {
        if (s < nk) {
            cp16(sA[s], Ag + s * 16);
            if (wload) cp16(sW[s], Wg + s * 16);
        }
        cp_commit();
    }

    int stage = 0;
    for (int kt = 0; kt < nk; kt++) {
        cp_wait<1>();
        __syncthreads();

        int ns = stage + 2; if (ns >= 3) ns -= 3;
        if (kt + 2 < nk) {
            cp16(sA[ns], Ag + (kt + 2) * 16);
            if (wload) cp16(sW[ns], Wg + (kt + 2) * 16);
        }
        cp_commit();

        const uint32_t* Ab = As[stage];
        const uint32_t* Wb = Ws[stage];

        uint32_t afr[2][4];
#pragma unroll
        for (int mf = 0; mf < 2; mf++) {
            int base = (warp_m * 32 + mf * 16 + gid) * BG_RS + tig;
            afr[mf][0] = Ab[base];
            afr[mf][1] = Ab[base + 8 * BG_RS];
            afr[mf][2] = Ab[base + 4];
            afr[mf][3] = Ab[base + 8 * BG_RS + 4];
        }
        uint32_t bfr[4][2];
#pragma unroll
        for (int nf = 0; nf < 4; nf++) {
            int base = (warp_n * 32 + nf * 8 + gid) * BG_RS + tig;
            bfr[nf][0] = Wb[base];
            bfr[nf][1] = Wb[base + 4];
        }
#pragma unroll
        for (int mf = 0; mf < 2; mf++)
#pragma unroll
            for (int nf = 0; nf < 4; nf++)
                mma_bf16(acc[mf][nf], afr[mf], bfr[nf]);

        stage++; if (stage == 3) stage = 0;
    }

#pragma unroll
    for (int mf = 0; mf < 2; mf++) {
        int r0 = brow + warp_m * 32 + mf * 16 + gid;
#pragma unroll
        for (int nf = 0; nf < 4; nf++) {
            int c0 = warp_n * 32 + nf * 8 + tig * 2;
            if (c0 < N) {
                *(float2*)(C + (size_t)r0 * N + c0) =
                    make_float2(acc[mf][nf][0], acc[mf][nf][1]);
                *(float2*)(C + (size_t)(r0 + 8) * N + c0) =
                    make_float2(acc[mf][nf][2], acc[mf][nf][3]);
            }
        }
    }
}

// ---------------- conv (k=4) + SiLU: dense xin, 4 ch/thread, dual store ----------------
__global__ void __launch_bounds__(128)
conv_silu_kernel(const float* __restrict__ xin, const float* __restrict__ cw,
                 const float* __restrict__ cb, float* __restrict__ xc,
                 bf16* __restrict__ xcb) {
    int bv = blockIdx.x;        // 32
    int chunk = blockIdx.y;     // 8 chunks of 128 t
    int tid = threadIdx.x;      // 128
    int dg = tid & 63;          // 64 groups of 4 d
    int tsub = tid >> 6;        // 0..1, each 64 t
    int d0 = dg * 4;
    int t0 = chunk * 128 + tsub * 64;

    float4 w0 = *(const float4*)(cw + (d0 + 0) * 4);
    float4 w1 = *(const float4*)(cw + (d0 + 1) * 4);
    float4 w2 = *(const float4*)(cw + (d0 + 2) * 4);
    float4 w3 = *(const float4*)(cw + (d0 + 3) * 4);
    float4 bb = *(const float4*)(cb + d0);

    const float* bx = xin + ((size_t)bv * SEQ) * DI + d0;
    float4 zero = make_float4(0.f, 0.f, 0.f, 0.f);
    float4 x0 = (t0 >= 3) ? *(const float4*)(bx + (size_t)(t0 - 3) * DI) : zero;
    float4 x1 = (t0 >= 2) ? *(const float4*)(bx + (size_t)(t0 - 2) * DI) : zero;
    float4 x2 = (t0 >= 1) ? *(const float4*)(bx + (size_t)(t0 - 1) * DI) : zero;

    float* oc = xc + ((size_t)bv * SEQ) * DI + d0;
    bf16* ob = xcb + ((size_t)bv * SEQ) * DI + d0;

#pragma unroll 4
    for (int tt = 0; tt < 64; tt++) {
        int t = t0 + tt;
        float4 x3 = *(const float4*)(bx + (size_t)t * DI);
        float4 v;
        v.x = fmaf(w0.x, x0.x, fmaf(w0.y, x1.x, fmaf(w0.z, x2.x, fmaf(w0.w, x3.x, bb.x))));
        v.y = fmaf(w1.x, x0.y, fmaf(w1.y, x1.y, fmaf(w1.z, x2.y, fmaf(w1.w, x3.y, bb.y))));
        v.z = fmaf(w2.x, x0.z, fmaf(w2.y, x1.z, fmaf(w2.z, x2.z, fmaf(w2.w, x3.z, bb.z))));
        v.w = fmaf(w3.x, x0.w, fmaf(w3.y, x1.w, fmaf(w3.z, x2.w, fmaf(w3.w, x3.w, bb.w))));
        float4 s;
        s.x = v.x / (1.0f + __expf(-v.x));
        s.y = v.y / (1.0f + __expf(-v.y));
        s.z = v.z / (1.0f + __expf(-v.z));
        s.w = v.w / (1.0f + __expf(-v.w));
        *(float4*)(oc + (size_t)t * DI) = s;
        *(__nv_bfloat162*)(ob + (size_t)t * DI)     = __float22bfloat162_rn(make_float2(s.x, s.y));
        *(__nv_bfloat162*)(ob + (size_t)t * DI + 2) = __float22bfloat162_rn(make_float2(s.z, s.w));
        x0 = x1; x1 = x2; x2 = x3;
    }
}

// ---------------- dt_proj (K=8) + fast softplus ----------------
__global__ void dt_softplus_kernel(const float* __restrict__ xdbl, const float* __restrict__ dtw,
                                   const float* __restrict__ dtb, float* __restrict__ delta) {
    __shared__ float dts[32][DTR];
    const int r0 = blockIdx.x * 32;
    const int tid = threadIdx.x;
    {
        int r = tid >> 3, c = tid & 7;
        dts[r][c] = xdbl[(size_t)(r0 + r) * 40 + c];
    }
    __syncthreads();
    const int d = tid;
    float w[DTR];
#pragma unroll
    for (int r = 0; r < DTR; r++) w[r] = dtw[d * DTR + r];
    const float b = dtb[d];
#pragma unroll 4
    for (int rr = 0; rr < 32; rr++) {
        float acc = b;
#pragma unroll
        for (int c = 0; c < DTR; c++) acc = fmaf(dts[rr][c], w[c], acc);
        float sp = fmaxf(acc, 0.f) + __logf(1.0f + __expf(-fabsf(acc)));
        delta[(size_t)(r0 + rr) * DI + d] = sp;
    }
}

// ---------------- selective scan: 4 states/lane, 8 d/warp, depth-8 prefetch ----------------
__global__ void __launch_bounds__(128)
scan_kernel(const float* __restrict__ xc, const float* __restrict__ delta,
            const float* __restrict__ xdbl, const bf16* __restrict__ zb,
            const float* __restrict__ A_log, const float* __restrict__ Dp,
            bf16* __restrict__ y) {
    const int PF = 8;
    int gw   = (blockIdx.x * 128 + threadIdx.x) >> 5;
    int lane = threadIdx.x & 31;
    int bv = gw >> 5;
    int dw = gw & 31;
    int g  = lane >> 2;
    int i  = lane & 3;
    int d  = dw * 8 + g;

    float4 al = *(const float4*)(A_log + d * DS + i * 4);
    float a0 = -__expf(al.x), a1 = -__expf(al.y), a2 = -__expf(al.z), a3 = -__expf(al.w);
    float Dval = Dp[d];
    float h0 = 0.f, h1 = 0.f, h2 = 0.f, h3 = 0.f;

    const float* pu  = xc    + (size_t)bv * SEQ * DI + d;
    const float* pdl = delta + (size_t)bv * SEQ * DI + d;
    const float* pB  = xdbl  + (size_t)bv * SEQ * 40 + DTR + i * 4;
    const float* pC  = pB + DS;
    const bf16*  pz  = zb    + (size_t)bv * SEQ * DI + d;
    bf16* py         = y     + (size_t)bv * SEQ * DI + d;

    float uf[PF], dlf[PF], zf[PF];
    float4 Bf[PF], Cf[PF];
#pragma unroll
    for (int k = 0; k < PF; k++) {
        uf[k]  = pu[k * DI];
        dlf[k] = pdl[k * DI];
        Bf[k]  = *(const float4*)(pB + k * 40);
        Cf[k]  = *(const float4*)(pC + k * 40);
        zf[k]  = __bfloat162float(pz[(size_t)k * DI]);
    }

    for (int t0 = 0; t0 < SEQ; t0 += PF) {
#pragma unroll
        for (int k = 0; k < PF; k++) {
            float u = uf[k], dl = dlf[k], silz = zf[k];
            float4 B = Bf[k], C = Cf[k];
            int tp = t0 + k + PF;
            if (tp < SEQ) {
                uf[k]  = pu[tp * DI];
                dlf[k] = pdl[tp * DI];
                Bf[k]  = *(const float4*)(pB + tp * 40);
                Cf[k]  = *(const float4*)(pC + tp * 40);
                zf[k]  = __bfloat162float(pz[(size_t)tp * DI]);
            }
            float dlu = dl * u;
            h0 = fmaf(__expf(dl * a0), h0, dlu * B.x);
            h1 = fmaf(__expf(dl * a1), h1, dlu * B.y);
            h2 = fmaf(__expf(dl * a2), h2, dlu * B.z);
            h3 = fmaf(__expf(dl * a3), h3, dlu * B.w);
            float p = h0 * C.x;
            p = fmaf(h1, C.y, p);
            p = fmaf(h2, C.z, p);
            p = fmaf(h3, C.w, p);
            p += __shfl_xor_sync(0xffffffffu, p, 1);
            p += __shfl_xor_sync(0xffffffffu, p, 2);
            if (i == 0) {
                py[(size_t)(t0 + k) * DI] = __float2bfloat16((p + u * Dval) * silz);
            }
        }
    }
}

// ---------------- final transpose: h[bv,n,dm] -> out[bv,dm,n] ----------------
__global__ void out_transpose_kernel(const float* __restrict__ hbuf, float* __restrict__ out) {
    __shared__ float tile[32][33];
    int bv = blockIdx.x, nc = blockIdx.y, dc = blockIdx.z;
    int tx = threadIdx.x, ty = threadIdx.y;
    tile[ty][tx] = hbuf[((size_t)bv * SEQ + nc * 32 + ty) * DMOD + dc * 32 + tx];
    __syncthreads();
    out[((size_t)bv * DMOD + dc * 32 + ty) * SEQ + nc * 32 + tx] = tile[tx][ty];
}

// ---------------- launch ----------------
extern "C" void kernel_launch(void* const* d_in, const int* in_sizes, int n_in,
                              void* d_out, int out_size) {
    const float* x         = (const float*)d_in[0];
    const float* W_P_w     = (const float*)d_in[1];
    const float* W_P_b     = (const float*)d_in[2];
    const float* in_proj_w = (const float*)d_in[3];
    const float* conv_w    = (const float*)d_in[4];
    const float* conv_b    = (const float*)d_in[5];
    const float* x_proj_w  = (const float*)d_in[6];
    const float* dt_proj_w = (const float*)d_in[7];
    const float* dt_proj_b = (const float*)d_in[8];
    const float* A_log     = (const float*)d_in[9];
    const float* Dp        = (const float*)d_in[10];
    const float* out_proj_w= (const float*)d_in[11];
    const float* lin1_w    = (const float*)d_in[12];
    const float* lin1_b    = (const float*)d_in[13];
    const float* lin2_w    = (const float*)d_in[14];
    const float* lin2_b    = (const float*)d_in[15];
    float* out = (float*)d_out;

    bf16 *hinb, *hb, *zb, *xcb, *yb, *h2b, *ffb;
    bf16 *wbP, *wbin, *wbout, *wbl1, *wbl2, *wbxp;
    float *h, *xin, *xc, *xdbl, *delta;
    cudaGetSymbolAddress((void**)&hinb,  g_hinb);
    cudaGetSymbolAddress((void**)&hb,    g_hb);
    cudaGetSymbolAddress((void**)&h,     g_h);
    cudaGetSymbolAddress((void**)&xin,   g_xin);
    cudaGetSymbolAddress((void**)&zb,    g_zb);
    cudaGetSymbolAddress((void**)&xc,    g_xc);
    cudaGetSymbolAddress((void**)&xcb,   g_xcb);
    cudaGetSymbolAddress((void**)&xdbl,  g_xdbl);
    cudaGetSymbolAddress((void**)&delta, g_delta);
    cudaGetSymbolAddress((void**)&yb,    g_yb);
    cudaGetSymbolAddress((void**)&h2b,   g_h2b);
    cudaGetSymbolAddress((void**)&ffb,   g_ffb);
    cudaGetSymbolAddress((void**)&wbP,   g_wbP);
    cudaGetSymbolAddress((void**)&wbin,  g_wbin);
    cudaGetSymbolAddress((void**)&wbout, g_wbout);
    cudaGetSymbolAddress((void**)&wbl1,  g_wbl1);
    cudaGetSymbolAddress((void**)&wbl2,  g_wbl2);
    cudaGetSymbolAddress((void**)&wbxp,  g_wbxp);

    // single batched weight convert
    {
        int n0 = DMOD * PLEN;          // 2048
        int n1 = 2 * 2 * DI * DMOD;    // 262144
        int n2 = 2 * DMOD * DI;        // 65536
        int n3 = 2 * DFF * DMOD;       // 65536
        int n4 = 2 * DMOD * DFF;       // 65536
        int n5 = 2 * 40 * DI;          // 20480
        int total = n0 + n1 + n2 + n3 + n4 + n5;
        f2b_all_kernel<<<(total / 2 + 255) / 256, 256>>>(
            W_P_w, wbP, n0, in_proj_w, wbin, n1, out_proj_w, wbout, n2,
            lin1_w, wbl1, n3, lin2_w, wbl2, n4, x_proj_w, wbxp, n5);
    }

    const int MT = NROWS / 128;

    patch_transpose_kernel<<<dim3(32, 16), 256>>>(x, hinb);
    bgemm_kernel<0, 2><<<dim3(1, MT), 256>>>(hinb, wbP, W_P_b, nullptr, hb, NROWS, DMOD, PLEN);

    for (int l = 0; l < 2; l++) {
        const bf16*  ipw = wbin  + (size_t)l * (2 * DI) * DMOD;
        const float* cwp = conv_w + (size_t)l * DI * 4;
        const float* cbp = conv_b + (size_t)l * DI;
        const bf16*  xpw = wbxp + (size_t)l * 40 * DI;
        const float* dpw = dt_proj_w + (size_t)l * DI * DTR;
        const float* dpb = dt_proj_b + (size_t)l * DI;
        const float* alg = A_log + (size_t)l * DI * DS;
        const float* dvp = Dp + (size_t)l * DI;
        const bf16*  opw = wbout + (size_t)l * DMOD * DI;
        const bf16*  l1w = wbl1 + (size_t)l * DFF * DMOD;
        const float* l1b = lin1_b + (size_t)l * DFF;
        const bf16*  l2w = wbl2 + (size_t)l * DMOD * DFF;
        const float* l2b = lin2_b + (size_t)l * DMOD;

        bgemm_kernel<0, 4><<<dim3(4, MT), 256>>>(hb, ipw, nullptr, xin, zb, NROWS, 2 * DI, DMOD);
        conv_silu_kernel<<<dim3(32, 8), 128>>>(xin, cwp, cbp, xc, xcb);
        bgemm64_kernel<<<dim3(1, MT), 256>>>(xcb, xpw, xdbl, NROWS, 40, DI);
        dt_softplus_kernel<<<NROWS / 32, 256>>>(xdbl, dpw, dpb, delta);
        scan_kernel<<<256, 128>>>(xc, delta, xdbl, zb, alg, dvp, yb);
        bgemm_kernel<0, 2><<<dim3(1, MT), 256>>>(yb, opw, nullptr, nullptr, h2b, NROWS, DMOD, DI);
        bgemm_kernel<1, 2><<<dim3(2, MT), 256>>>(h2b, l1w, l1b, nullptr, ffb, NROWS, DFF, DMOD);
        bgemm_kernel<0, 3><<<dim3(1, MT), 256>>>(ffb, l2w, l2b, h, hb, NROWS, DMOD, DFF);
    }

    out_transpose_kernel<<<dim3(32, 32, 4), dim3(32, 32)>>>(h, out);
}